// round 7
// baseline (speedup 1.0000x reference)
#include <cuda_runtime.h>
#include <cuda_bf16.h>
#include <mma.h>
#include <cstdint>

using namespace nvcuda;

#define SQ   2048
#define BB   8
#define DD   512
#define HH   8
#define HDIM 64
#define MROWS (SQ*BB)       // 16384
#define BH    (BB*HH)       // 64
#define STRD 72             // 144B rows: conflict-free 8-row LDSM phases
#define STRD40 40           // 80B rows: conflict-free, for K=32 chunks

// ---------------- scratch (__device__ globals) -----------------------------
__device__ __nv_bfloat16 g_shi[(size_t)MROWS*DD];
__device__ __nv_bfloat16 g_slo[(size_t)MROWS*DD];
__device__ __nv_bfloat16 g_wihi[(size_t)3*DD*DD];
__device__ __nv_bfloat16 g_wilo[(size_t)3*DD*DD];
__device__ __nv_bfloat16 g_wohi[(size_t)DD*DD];
__device__ __nv_bfloat16 g_wolo[(size_t)DD*DD];
__device__ __nv_bfloat16 g_qhi[(size_t)BH*SQ*HDIM];
__device__ __nv_bfloat16 g_qlo[(size_t)BH*SQ*HDIM];
__device__ __nv_bfloat16 g_khi[(size_t)BH*SQ*HDIM];
__device__ __nv_bfloat16 g_klo[(size_t)BH*SQ*HDIM];
__device__ __nv_bfloat16 g_vhi[(size_t)BH*SQ*HDIM];
__device__ __nv_bfloat16 g_vlo[(size_t)BH*SQ*HDIM];
__device__ float g_scores[(size_t)BH*SQ*SQ];
__device__ float g_rowinv[(size_t)BH*SQ];
__device__ __nv_bfloat16 g_cthi[(size_t)MROWS*DD];
__device__ __nv_bfloat16 g_ctlo[(size_t)MROWS*DD];

__device__ __forceinline__ void split2(float x0, float x1, uint32_t& hi, uint32_t& lo) {
    __nv_bfloat16 h0 = __float2bfloat16(x0), h1 = __float2bfloat16(x1);
    float r0 = x0 - __bfloat162float(h0), r1 = x1 - __bfloat162float(h1);
    __nv_bfloat162 H = __halves2bfloat162(h0, h1);
    __nv_bfloat162 L = __halves2bfloat162(__float2bfloat16(r0), __float2bfloat16(r1));
    hi = *(uint32_t*)&H;
    lo = *(uint32_t*)&L;
}
__device__ __forceinline__ uint32_t smem_u32(const void* p) {
    uint32_t a;
    asm("{ .reg .u64 t; cvta.to.shared.u64 t, %1; cvt.u32.u64 %0, t; }" : "=r"(a) : "l"(p));
    return a;
}
__device__ __forceinline__ void cpa16(uint32_t dst, const void* src) {
    asm volatile("cp.async.cg.shared.global [%0], [%1], 16;" :: "r"(dst), "l"(src));
}
#define CP_COMMIT asm volatile("cp.async.commit_group;" ::: "memory")
#define CP_WAIT0  asm volatile("cp.async.wait_group 0;" ::: "memory")
#define CP_WAIT1  asm volatile("cp.async.wait_group 1;" ::: "memory")

typedef wmma::fragment<wmma::matrix_a, 16, 16, 16, __nv_bfloat16, wmma::row_major> FragA;
typedef wmma::fragment<wmma::matrix_b, 16, 16, 16, __nv_bfloat16, wmma::col_major> FragBc;
typedef wmma::fragment<wmma::matrix_b, 16, 16, 16, __nv_bfloat16, wmma::row_major> FragBr;
typedef wmma::fragment<wmma::accumulator, 16, 16, 16, float> FragC;

// ---------------------------------------------------------------------------
// K0: elementwise fp32 -> split bf16
// ---------------------------------------------------------------------------
__global__ void split_f32(const float* __restrict__ in, __nv_bfloat16* __restrict__ hi,
                          __nv_bfloat16* __restrict__ lo, int n4) {
    int i = blockIdx.x * blockDim.x + threadIdx.x;
    if (i >= n4) return;
    float4 v = ((const float4*)in)[i];
    uint32_t h01, l01, h23, l23;
    split2(v.x, v.y, h01, l01);
    split2(v.z, v.w, h23, l23);
    ((uint2*)hi)[i] = make_uint2(h01, h23);
    ((uint2*)lo)[i] = make_uint2(l01, l23);
}

// ---------------------------------------------------------------------------
// Shared GEMM body for qkv/out: CTA 128(m) x 64(n), K-chunks of 32, 2-stage.
// stage elems: Ah 5120, Al 5120, Bh 2560, Bl 2560 = 15360 (30KB); x2 = 60KB.
// ---------------------------------------------------------------------------
#define PROJ_STG 15360

template <bool kOut>
__device__ __forceinline__ void proj_body(int m0, int n0, int nK, FragC acc[2][2],
                                          __nv_bfloat16* sm, uint32_t smb,
                                          const __nv_bfloat16* gah, const __nv_bfloat16* gal,
                                          const __nv_bfloat16* gbh, const __nv_bfloat16* gbl) {
    int tid = threadIdx.x;
    int wid = tid >> 5;
    int wy = wid & 3, wx = wid >> 2;

    auto load_stage = [&](int st, int k0) {
        uint32_t base = smb + st * PROJ_STG * 2;
        #pragma unroll
        for (int l = 0; l < 2; l++) {
            int idx = tid + l * 256;
            int r = idx >> 2, c = idx & 3;
            size_t g = (size_t)(m0 + r) * DD + k0 + c * 8;
            uint32_t d = base + (r * STRD40 + c * 8) * 2;
            cpa16(d, &gah[g]);
            cpa16(d + 5120 * 2, &gal[g]);
        }
        {
            int r = tid >> 2, c = tid & 3;
            size_t g = (size_t)(n0 + r) * DD + c * 8 + k0;
            uint32_t d = base + (10240 + r * STRD40 + c * 8) * 2;
            cpa16(d, &gbh[g]);
            cpa16(d + 2560 * 2, &gbl[g]);
        }
        CP_COMMIT;
    };

    int niter = nK / 32;
    load_stage(0, 0);
    for (int kt = 0; kt < niter; kt++) {
        if (kt + 1 < niter) { load_stage((kt + 1) & 1, (kt + 1) * 32); CP_WAIT1; }
        else CP_WAIT0;
        __syncthreads();
        const __nv_bfloat16* Ah = sm + (kt & 1) * PROJ_STG;
        const __nv_bfloat16* Al = Ah + 5120;
        const __nv_bfloat16* Bh = Ah + 10240;
        const __nv_bfloat16* Bl = Ah + 12800;
        #pragma unroll
        for (int kk = 0; kk < 2; kk++) {
            FragA  ah[2], al[2];
            FragBc bh[2], bl[2];
            #pragma unroll
            for (int i = 0; i < 2; i++) {
                wmma::load_matrix_sync(ah[i], Ah + (wy * 32 + i * 16) * STRD40 + kk * 16, STRD40);
                wmma::load_matrix_sync(al[i], Al + (wy * 32 + i * 16) * STRD40 + kk * 16, STRD40);
            }
            #pragma unroll
            for (int j = 0; j < 2; j++) {
                wmma::load_matrix_sync(bh[j], Bh + (wx * 32 + j * 16) * STRD40 + kk * 16, STRD40);
                wmma::load_matrix_sync(bl[j], Bl + (wx * 32 + j * 16) * STRD40 + kk * 16, STRD40);
            }
            #pragma unroll
            for (int i = 0; i < 2; i++)
                #pragma unroll
                for (int j = 0; j < 2; j++) {
                    wmma::mma_sync(acc[i][j], ah[i], bh[j], acc[i][j]);
                    wmma::mma_sync(acc[i][j], ah[i], bl[j], acc[i][j]);
                    wmma::mma_sync(acc[i][j], al[i], bh[j], acc[i][j]);
                }
        }
        __syncthreads();
    }
}

// K1: QKV projection
__global__ void __launch_bounds__(256, 2) qkv_wmma(const float* __restrict__ bias) {
    extern __shared__ __align__(16) unsigned char dynsm[];
    __nv_bfloat16* sm = (__nv_bfloat16*)dynsm;
    uint32_t smb = smem_u32(dynsm);
    int tid = threadIdx.x;
    int wid = tid >> 5;
    int wy = wid & 3, wx = wid >> 2;
    int n0 = blockIdx.x * 64, m0 = blockIdx.y * 128;

    FragC acc[2][2];
    #pragma unroll
    for (int i = 0; i < 2; i++)
        #pragma unroll
        for (int j = 0; j < 2; j++) wmma::fill_fragment(acc[i][j], 0.0f);

    proj_body<false>(m0, n0, DD, acc, sm, smb, g_shi, g_slo, g_wihi, g_wilo);

    float* stage = (float*)dynsm;    // 128 x 68
    #pragma unroll
    for (int i = 0; i < 2; i++)
        #pragma unroll
        for (int j = 0; j < 2; j++)
            wmma::store_matrix_sync(stage + (wy * 32 + i * 16) * 68 + wx * 32 + j * 16,
                                    acc[i][j], 68, wmma::mem_row_major);
    __syncthreads();

    int row = tid >> 1, half = (tid & 1) * 32;
    int part = n0 >> 9;
    int h = (n0 >> 6) & 7;
    int i = m0 + row;
    int s = i >> 3, b = i & 7;
    int bh = b * HH + h;
    float scale = (part == 0) ? 0.125f : 1.0f;
    size_t obase = ((size_t)bh * SQ + s) * HDIM + half;
    __nv_bfloat16* ph = (part == 0) ? g_qhi : (part == 1) ? g_khi : g_vhi;
    __nv_bfloat16* pl = (part == 0) ? g_qlo : (part == 1) ? g_klo : g_vlo;
    #pragma unroll
    for (int j = 0; j < 8; j++) {
        float4 v = *(float4*)&stage[row * 68 + half + j * 4];
        int col = n0 + half + j * 4;
        v.x = (v.x + bias[col]) * scale;
        v.y = (v.y + bias[col + 1]) * scale;
        v.z = (v.z + bias[col + 2]) * scale;
        v.w = (v.w + bias[col + 3]) * scale;
        uint32_t h01, l01, h23, l23;
        split2(v.x, v.y, h01, l01);
        split2(v.z, v.w, h23, l23);
        *(uint2*)(ph + obase + j * 4) = make_uint2(h01, h23);
        *(uint2*)(pl + obase + j * 4) = make_uint2(l01, l23);
    }
}

// K5: out projection
__global__ void __launch_bounds__(256, 2) out_wmma(const float* __restrict__ bias,
                                                   float* __restrict__ out) {
    extern __shared__ __align__(16) unsigned char dynsm[];
    __nv_bfloat16* sm = (__nv_bfloat16*)dynsm;
    uint32_t smb = smem_u32(dynsm);
    int tid = threadIdx.x;
    int wid = tid >> 5;
    int wy = wid & 3, wx = wid >> 2;
    int n0 = blockIdx.x * 64, m0 = blockIdx.y * 128;

    FragC acc[2][2];
    #pragma unroll
    for (int i = 0; i < 2; i++)
        #pragma unroll
        for (int j = 0; j < 2; j++) wmma::fill_fragment(acc[i][j], 0.0f);

    proj_body<true>(m0, n0, DD, acc, sm, smb, g_cthi, g_ctlo, g_wohi, g_wolo);

    float* stage = (float*)dynsm;
    #pragma unroll
    for (int i = 0; i < 2; i++)
        #pragma unroll
        for (int j = 0; j < 2; j++)
            wmma::store_matrix_sync(stage + (wy * 32 + i * 16) * 68 + wx * 32 + j * 16,
                                    acc[i][j], 68, wmma::mem_row_major);
    __syncthreads();

    int row = tid >> 1, half = (tid & 1) * 32;
    #pragma unroll
    for (int j = 0; j < 8; j++) {
        float4 v = *(float4*)&stage[row * 68 + half + j * 4];
        int col = n0 + half + j * 4;
        v.x += bias[col]; v.y += bias[col + 1]; v.z += bias[col + 2]; v.w += bias[col + 3];
        *(float4*)&out[(size_t)(m0 + row) * DD + col] = v;
    }
}

// ---------------------------------------------------------------------------
// K2: scores = Q.K^T. CTA 128(s) x 64(t), K=64 one-shot. smem 54KB.
// ---------------------------------------------------------------------------
__global__ void __launch_bounds__(256, 2) scores_wmma() {
    extern __shared__ __align__(16) unsigned char dynsm[];
    __nv_bfloat16* sm = (__nv_bfloat16*)dynsm;
    uint32_t smb = smem_u32(dynsm);

    int tid = threadIdx.x;
    int wid = tid >> 5;
    int wy = wid & 3, wx = wid >> 2;
    int bh = blockIdx.z;
    int s0 = blockIdx.y * 128;
    int t0 = blockIdx.x * 64;

    #pragma unroll
    for (int l = 0; l < 4; l++) {
        int idx = tid + l * 256;
        int r = idx >> 3, c = idx & 7;
        size_t g = ((size_t)bh * SQ + s0 + r) * HDIM + c * 8;
        uint32_t d = smb + (r * STRD + c * 8) * 2;
        cpa16(d, &g_qhi[g]);
        cpa16(d + 9216 * 2, &g_qlo[g]);
    }
    #pragma unroll
    for (int l = 0; l < 2; l++) {
        int idx = tid + l * 256;
        int r = idx >> 3, c = idx & 7;
        size_t g = ((size_t)bh * SQ + t0 + r) * HDIM + c * 8;
        uint32_t d = smb + (18432 + r * STRD + c * 8) * 2;
        cpa16(d, &g_khi[g]);
        cpa16(d + 4608 * 2, &g_klo[g]);
    }
    CP_COMMIT;
    CP_WAIT0;
    __syncthreads();

    const __nv_bfloat16* Qh = sm;
    const __nv_bfloat16* Ql = sm + 9216;
    const __nv_bfloat16* Kh = sm + 18432;
    const __nv_bfloat16* Kl = sm + 23040;

    FragC acc[2][2];
    #pragma unroll
    for (int i = 0; i < 2; i++)
        #pragma unroll
        for (int j = 0; j < 2; j++) wmma::fill_fragment(acc[i][j], 0.0f);

    #pragma unroll
    for (int kk = 0; kk < 4; kk++) {
        FragA  ah[2], al[2];
        FragBc bh_[2], bl_[2];
        #pragma unroll
        for (int i = 0; i < 2; i++) {
            wmma::load_matrix_sync(ah[i], Qh + (wy * 32 + i * 16) * STRD + kk * 16, STRD);
            wmma::load_matrix_sync(al[i], Ql + (wy * 32 + i * 16) * STRD + kk * 16, STRD);
        }
        #pragma unroll
        for (int j = 0; j < 2; j++) {
            wmma::load_matrix_sync(bh_[j], Kh + (wx * 32 + j * 16) * STRD + kk * 16, STRD);
            wmma::load_matrix_sync(bl_[j], Kl + (wx * 32 + j * 16) * STRD + kk * 16, STRD);
        }
        #pragma unroll
        for (int i = 0; i < 2; i++)
            #pragma unroll
            for (int j = 0; j < 2; j++) {
                wmma::mma_sync(acc[i][j], ah[i], bh_[j], acc[i][j]);
                wmma::mma_sync(acc[i][j], ah[i], bl_[j], acc[i][j]);
                wmma::mma_sync(acc[i][j], al[i], bh_[j], acc[i][j]);
            }
    }
    #pragma unroll
    for (int i = 0; i < 2; i++)
        #pragma unroll
        for (int j = 0; j < 2; j++) {
            float* out = g_scores + ((size_t)bh * SQ + s0 + wy * 32 + i * 16) * SQ + t0 + wx * 32 + j * 16;
            wmma::store_matrix_sync(out, acc[i][j], SQ, wmma::mem_row_major);
        }
}

// ---------------------------------------------------------------------------
// K3: ctx = exp(scores) @ V. CTA 128(s) x 64(d); P single-buffer, V 2-stage.
// smem: Ph 9216, Pl 9216, V 2x(4608+4608) = 36864 elems = 72KB.
// ---------------------------------------------------------------------------
__global__ void __launch_bounds__(256, 2) ctx_wmma() {
    extern __shared__ __align__(16) unsigned char dynsm[];
    __nv_bfloat16* sm = (__nv_bfloat16*)dynsm;
    uint32_t smb = smem_u32(dynsm);

    int tid = threadIdx.x;
    int wid = tid >> 5;
    int wy = wid & 3, wx = wid >> 2;
    int bh = blockIdx.y;
    int s0 = blockIdx.x * 128;

    int row = tid >> 1, half = (tid & 1) * 32;
    const float* prow = g_scores + ((size_t)bh * SQ + s0 + row) * SQ + half;

    auto load_v = [&](int st, int c) {
        #pragma unroll
        for (int l = 0; l < 2; l++) {
            int idx = tid + l * 256;
            int r = idx >> 3, c8 = idx & 7;
            size_t g = ((size_t)bh * SQ + c * 64 + r) * HDIM + c8 * 8;
            uint32_t d = smb + (18432 + st * 9216 + r * STRD + c8 * 8) * 2;
            cpa16(d, &g_vhi[g]);
            cpa16(d + 4608 * 2, &g_vlo[g]);
        }
        CP_COMMIT;
    };

    FragC acc[2][2];
    #pragma unroll
    for (int i = 0; i < 2; i++)
        #pragma unroll
        for (int j = 0; j < 2; j++) wmma::fill_fragment(acc[i][j], 0.0f);

    float4 cur[8];
    #pragma unroll
    for (int j = 0; j < 8; j++) cur[j] = *(const float4*)&prow[j * 4];
    load_v(0, 0);

    __nv_bfloat16* Ph = sm;
    __nv_bfloat16* Pl = sm + 9216;

    float rowsum = 0.0f;
    for (int c = 0; c < 32; c++) {
        int st = c & 1;
        if (c + 1 < 32) load_v((c + 1) & 1, c + 1);
        #pragma unroll
        for (int j = 0; j < 8; j++) {
            float e0 = __expf(cur[j].x), e1 = __expf(cur[j].y);
            float e2 = __expf(cur[j].z), e3 = __expf(cur[j].w);
            rowsum += (e0 + e1) + (e2 + e3);
            uint32_t h01, l01, h23, l23;
            split2(e0, e1, h01, l01);
            split2(e2, e3, h23, l23);
            *(uint2*)&Ph[row * STRD + half + j * 4] = make_uint2(h01, h23);
            *(uint2*)&Pl[row * STRD + half + j * 4] = make_uint2(l01, l23);
        }
        if (c + 1 < 32) {
            #pragma unroll
            for (int j = 0; j < 8; j++) cur[j] = *(const float4*)&prow[(c + 1) * 64 + j * 4];
            CP_WAIT1;
        } else CP_WAIT0;
        __syncthreads();
        const __nv_bfloat16* Vh = sm + 18432 + st * 9216;
        const __nv_bfloat16* Vl = Vh + 4608;
        #pragma unroll
        for (int kk = 0; kk < 4; kk++) {
            FragA  ah[2], al[2];
            FragBr bh_[2], bl_[2];
            #pragma unroll
            for (int i = 0; i < 2; i++) {
                wmma::load_matrix_sync(ah[i], Ph + (wy * 32 + i * 16) * STRD + kk * 16, STRD);
                wmma::load_matrix_sync(al[i], Pl + (wy * 32 + i * 16) * STRD + kk * 16, STRD);
            }
            #pragma unroll
            for (int j = 0; j < 2; j++) {
                wmma::load_matrix_sync(bh_[j], Vh + (kk * 16) * STRD + wx * 32 + j * 16, STRD);
                wmma::load_matrix_sync(bl_[j], Vl + (kk * 16) * STRD + wx * 32 + j * 16, STRD);
            }
            #pragma unroll
            for (int i = 0; i < 2; i++)
                #pragma unroll
                for (int j = 0; j < 2; j++) {
                    wmma::mma_sync(acc[i][j], ah[i], bh_[j], acc[i][j]);
                    wmma::mma_sync(acc[i][j], ah[i], bl_[j], acc[i][j]);
                    wmma::mma_sync(acc[i][j], al[i], bh_[j], acc[i][j]);
                }
        }
        __syncthreads();
    }

    float tot = rowsum + __shfl_xor_sync(0xFFFFFFFFu, rowsum, 1);
    float inv = 1.0f / tot;
    if (!(tid & 1)) g_rowinv[(size_t)bh * SQ + s0 + row] = inv;

    float* stage = (float*)dynsm;   // 128 x 68
    __syncthreads();
    #pragma unroll
    for (int i = 0; i < 2; i++)
        #pragma unroll
        for (int j = 0; j < 2; j++)
            wmma::store_matrix_sync(stage + (wy * 32 + i * 16) * 68 + wx * 32 + j * 16,
                                    acc[i][j], 68, wmma::mem_row_major);
    __syncthreads();

    int b = bh >> 3, h = bh & 7;
    size_t obase = ((size_t)(s0 + row) * BB + b) * DD + h * HDIM + half;
    #pragma unroll
    for (int j = 0; j < 8; j++) {
        float4 v = *(float4*)&stage[row * 68 + half + j * 4];
        uint32_t h01, l01, h23, l23;
        split2(v.x * inv, v.y * inv, h01, l01);
        split2(v.z * inv, v.w * inv, h23, l23);
        *(uint2*)(g_cthi + obase + j * 4) = make_uint2(h01, h23);
        *(uint2*)(g_ctlo + obase + j * 4) = make_uint2(l01, l23);
    }
}

// ---------------------------------------------------------------------------
// K4: attn_weights = mean_h exp(scores) * rowinv  (float4 vectorized)
// ---------------------------------------------------------------------------
__global__ void head_avg(float* __restrict__ out_attn) {
    size_t i = (size_t)blockIdx.x * blockDim.x + threadIdx.x;
    size_t n4 = (size_t)BB * SQ * SQ / 4;
    if (i >= n4) return;
    size_t plane4 = (size_t)SQ * SQ / 4;
    size_t b    = i / plane4;
    size_t rem4 = i % plane4;
    size_t s    = rem4 / (SQ / 4);
    float4 sum = make_float4(0.f, 0.f, 0.f, 0.f);
    #pragma unroll
    for (int h = 0; h < HH; h++) {
        size_t bh = b * HH + h;
        float4 v = *((const float4*)(g_scores + bh * SQ * SQ) + rem4);
        float inv = g_rowinv[bh * SQ + s];
        sum.x += __expf(v.x) * inv;
        sum.y += __expf(v.y) * inv;
        sum.z += __expf(v.z) * inv;
        sum.w += __expf(v.w) * inv;
    }
    sum.x *= 0.125f; sum.y *= 0.125f; sum.z *= 0.125f; sum.w *= 0.125f;
    ((float4*)out_attn)[i] = sum;
}

extern "C" void kernel_launch(void* const* d_in, const int* in_sizes, int n_in,
                              void* d_out, int out_size) {
    const float* src   = (const float*)d_in[0];
    const float* in_w  = (const float*)d_in[1];
    const float* in_b  = (const float*)d_in[2];
    const float* out_w = (const float*)d_in[3];
    const float* out_b = (const float*)d_in[4];
    float* out      = (float*)d_out;
    float* attn_out = out + (size_t)SQ * BB * DD;

    __nv_bfloat16 *shi, *slo, *wihi, *wilo, *wohi, *wolo;
    cudaGetSymbolAddress((void**)&shi,  g_shi);
    cudaGetSymbolAddress((void**)&slo,  g_slo);
    cudaGetSymbolAddress((void**)&wihi, g_wihi);
    cudaGetSymbolAddress((void**)&wilo, g_wilo);
    cudaGetSymbolAddress((void**)&wohi, g_wohi);
    cudaGetSymbolAddress((void**)&wolo, g_wolo);

    const int SM_PROJ  = 2 * PROJ_STG * 2;   // 61440
    const int SM_SCORE = 27648 * 2;          // 55296
    const int SM_CTX   = 36864 * 2;          // 73728
    cudaFuncSetAttribute(qkv_wmma,    cudaFuncAttributeMaxDynamicSharedMemorySize, SM_PROJ);
    cudaFuncSetAttribute(out_wmma,    cudaFuncAttributeMaxDynamicSharedMemorySize, SM_PROJ);
    cudaFuncSetAttribute(scores_wmma, cudaFuncAttributeMaxDynamicSharedMemorySize, SM_SCORE);
    cudaFuncSetAttribute(ctx_wmma,    cudaFuncAttributeMaxDynamicSharedMemorySize, SM_CTX);

    int n4s = MROWS * DD / 4, n4i = 3 * DD * DD / 4, n4o = DD * DD / 4;
    split_f32<<<(n4s + 255) / 256, 256>>>(src,  shi,  slo,  n4s);
    split_f32<<<(n4i + 255) / 256, 256>>>(in_w, wihi, wilo, n4i);
    split_f32<<<(n4o + 255) / 256, 256>>>(out_w, wohi, wolo, n4o);

    qkv_wmma<<<dim3(3 * DD / 64, MROWS / 128), 256, SM_PROJ>>>(in_b);
    scores_wmma<<<dim3(SQ / 64, SQ / 128, BH), 256, SM_SCORE>>>();
    ctx_wmma<<<dim3(SQ / 128, BH), 256, SM_CTX>>>();
    head_avg<<<(unsigned)(((size_t)BB * SQ * SQ / 4 + 255) / 256), 256>>>(attn_out);
    out_wmma<<<dim3(DD / 64, MROWS / 128), 256, SM_PROJ>>>(out_b, out);
}

// round 9
// speedup vs baseline: 1.4835x; 1.4835x over previous
#include <cuda_runtime.h>
#include <cuda_bf16.h>
#include <mma.h>
#include <cstdint>

using namespace nvcuda;

#define SQ   2048
#define BB   8
#define DD   512
#define HH   8
#define HDIM 64
#define MROWS (SQ*BB)       // 16384
#define BH    (BB*HH)       // 64
#define STRD 72             // 144B rows: conflict-free 8-row LDSM phases

// ---------------- scratch (__device__ globals) -----------------------------
__device__ __nv_bfloat16 g_shi[(size_t)MROWS*DD];
__device__ __nv_bfloat16 g_slo[(size_t)MROWS*DD];
__device__ __nv_bfloat16 g_wihi[(size_t)3*DD*DD];
__device__ __nv_bfloat16 g_wilo[(size_t)3*DD*DD];
__device__ __nv_bfloat16 g_wohi[(size_t)DD*DD];
__device__ __nv_bfloat16 g_wolo[(size_t)DD*DD];
__device__ __nv_bfloat16 g_qhi[(size_t)BH*SQ*HDIM];
__device__ __nv_bfloat16 g_qlo[(size_t)BH*SQ*HDIM];
__device__ __nv_bfloat16 g_khi[(size_t)BH*SQ*HDIM];
__device__ __nv_bfloat16 g_klo[(size_t)BH*SQ*HDIM];
__device__ __nv_bfloat16 g_vhi[(size_t)BH*SQ*HDIM];
__device__ __nv_bfloat16 g_vlo[(size_t)BH*SQ*HDIM];
__device__ float g_scores[(size_t)BH*SQ*SQ];
__device__ float g_rowinv[(size_t)BH*SQ];
__device__ __nv_bfloat16 g_cthi[(size_t)MROWS*DD];
__device__ __nv_bfloat16 g_ctlo[(size_t)MROWS*DD];

__device__ __forceinline__ void split2(float x0, float x1, uint32_t& hi, uint32_t& lo) {
    __nv_bfloat16 h0 = __float2bfloat16(x0), h1 = __float2bfloat16(x1);
    float r0 = x0 - __bfloat162float(h0), r1 = x1 - __bfloat162float(h1);
    __nv_bfloat162 H = __halves2bfloat162(h0, h1);
    __nv_bfloat162 L = __halves2bfloat162(__float2bfloat16(r0), __float2bfloat16(r1));
    hi = *(uint32_t*)&H;
    lo = *(uint32_t*)&L;
}
__device__ __forceinline__ uint32_t smem_u32(const void* p) {
    uint32_t a;
    asm("{ .reg .u64 t; cvta.to.shared.u64 t, %1; cvt.u32.u64 %0, t; }" : "=r"(a) : "l"(p));
    return a;
}
__device__ __forceinline__ void cpa16(uint32_t dst, const void* src) {
    asm volatile("cp.async.cg.shared.global [%0], [%1], 16;" :: "r"(dst), "l"(src));
}
#define CP_COMMIT asm volatile("cp.async.commit_group;" ::: "memory")
#define CP_WAIT0  asm volatile("cp.async.wait_group 0;" ::: "memory")
#define CP_WAIT1  asm volatile("cp.async.wait_group 1;" ::: "memory")

typedef wmma::fragment<wmma::matrix_a, 16, 16, 16, __nv_bfloat16, wmma::row_major> FragA;
typedef wmma::fragment<wmma::matrix_b, 16, 16, 16, __nv_bfloat16, wmma::col_major> FragBc;
typedef wmma::fragment<wmma::matrix_b, 16, 16, 16, __nv_bfloat16, wmma::row_major> FragBr;
typedef wmma::fragment<wmma::accumulator, 16, 16, 16, float> FragC;

// ---------------------------------------------------------------------------
// K0: elementwise fp32 -> split bf16
// ---------------------------------------------------------------------------
__global__ void split_f32(const float* __restrict__ in, __nv_bfloat16* __restrict__ hi,
                          __nv_bfloat16* __restrict__ lo, int n4) {
    int i = blockIdx.x * blockDim.x + threadIdx.x;
    if (i >= n4) return;
    float4 v = ((const float4*)in)[i];
    uint32_t h01, l01, h23, l23;
    split2(v.x, v.y, h01, l01);
    split2(v.z, v.w, h23, l23);
    ((uint2*)hi)[i] = make_uint2(h01, h23);
    ((uint2*)lo)[i] = make_uint2(l01, l23);
}

// ---------------------------------------------------------------------------
// Projection body: CTA 128(m) x 64(n), K chunks of 64, single-stage smem
// (Ah 9216 | Al 9216 | Bh 4608 | Bl 4608 = 27648 elems = 54KB) -> 2 CTAs/SM.
// ---------------------------------------------------------------------------
__device__ __forceinline__ void proj_body(int m0, int n0, FragC acc[2][2],
                                          __nv_bfloat16* sm, uint32_t smb,
                                          const __nv_bfloat16* gah, const __nv_bfloat16* gal,
                                          const __nv_bfloat16* gbh, const __nv_bfloat16* gbl) {
    int tid = threadIdx.x;
    int wid = tid >> 5;
    int wy = wid & 3, wx = wid >> 2;

    const __nv_bfloat16* Ah = sm;
    const __nv_bfloat16* Al = sm + 9216;
    const __nv_bfloat16* Bh = sm + 18432;
    const __nv_bfloat16* Bl = sm + 23040;

    for (int kt = 0; kt < 8; kt++) {
        int k0 = kt * 64;
        #pragma unroll
        for (int l = 0; l < 4; l++) {
            int idx = tid + l * 256;
            int r = idx >> 3, c = idx & 7;
            size_t g = (size_t)(m0 + r) * DD + k0 + c * 8;
            uint32_t d = smb + (r * STRD + c * 8) * 2;
            cpa16(d, &gah[g]);
            cpa16(d + 9216 * 2, &gal[g]);
        }
        #pragma unroll
        for (int l = 0; l < 2; l++) {
            int idx = tid + l * 256;
            int r = idx >> 3, c = idx & 7;
            size_t g = (size_t)(n0 + r) * DD + k0 + c * 8;
            uint32_t d = smb + (18432 + r * STRD + c * 8) * 2;
            cpa16(d, &gbh[g]);
            cpa16(d + 4608 * 2, &gbl[g]);
        }
        CP_COMMIT;
        CP_WAIT0;
        __syncthreads();
        #pragma unroll
        for (int kk = 0; kk < 4; kk++) {
            FragA  ah[2], al[2];
            FragBc bh[2], bl[2];
            #pragma unroll
            for (int i = 0; i < 2; i++) {
                wmma::load_matrix_sync(ah[i], Ah + (wy * 32 + i * 16) * STRD + kk * 16, STRD);
                wmma::load_matrix_sync(al[i], Al + (wy * 32 + i * 16) * STRD + kk * 16, STRD);
            }
            #pragma unroll
            for (int j = 0; j < 2; j++) {
                wmma::load_matrix_sync(bh[j], Bh + (wx * 32 + j * 16) * STRD + kk * 16, STRD);
                wmma::load_matrix_sync(bl[j], Bl + (wx * 32 + j * 16) * STRD + kk * 16, STRD);
            }
            #pragma unroll
            for (int i = 0; i < 2; i++)
                #pragma unroll
                for (int j = 0; j < 2; j++) {
                    wmma::mma_sync(acc[i][j], ah[i], bh[j], acc[i][j]);
                    wmma::mma_sync(acc[i][j], ah[i], bl[j], acc[i][j]);
                    wmma::mma_sync(acc[i][j], al[i], bh[j], acc[i][j]);
                }
        }
        __syncthreads();
    }
}

// K1: QKV projection
__global__ void __launch_bounds__(256, 2) qkv_wmma(const float* __restrict__ bias) {
    extern __shared__ __align__(16) unsigned char dynsm[];
    __nv_bfloat16* sm = (__nv_bfloat16*)dynsm;
    uint32_t smb = smem_u32(dynsm);
    int tid = threadIdx.x;
    int wid = tid >> 5;
    int wy = wid & 3, wx = wid >> 2;
    int n0 = blockIdx.x * 64, m0 = blockIdx.y * 128;

    FragC acc[2][2];
    #pragma unroll
    for (int i = 0; i < 2; i++)
        #pragma unroll
        for (int j = 0; j < 2; j++) wmma::fill_fragment(acc[i][j], 0.0f);

    proj_body(m0, n0, acc, sm, smb, g_shi, g_slo, g_wihi, g_wilo);

    float* stage = (float*)dynsm;    // 128 x 68
    #pragma unroll
    for (int i = 0; i < 2; i++)
        #pragma unroll
        for (int j = 0; j < 2; j++)
            wmma::store_matrix_sync(stage + (wy * 32 + i * 16) * 68 + wx * 32 + j * 16,
                                    acc[i][j], 68, wmma::mem_row_major);
    __syncthreads();

    int row = tid >> 1, half = (tid & 1) * 32;
    int part = n0 >> 9;
    int h = (n0 >> 6) & 7;
    int i = m0 + row;
    int s = i >> 3, b = i & 7;
    int bh = b * HH + h;
    float scale = (part == 0) ? 0.125f : 1.0f;
    size_t obase = ((size_t)bh * SQ + s) * HDIM + half;
    __nv_bfloat16* ph = (part == 0) ? g_qhi : (part == 1) ? g_khi : g_vhi;
    __nv_bfloat16* pl = (part == 0) ? g_qlo : (part == 1) ? g_klo : g_vlo;
    #pragma unroll
    for (int j = 0; j < 8; j++) {
        float4 v = *(float4*)&stage[row * 68 + half + j * 4];
        int col = n0 + half + j * 4;
        v.x = (v.x + bias[col]) * scale;
        v.y = (v.y + bias[col + 1]) * scale;
        v.z = (v.z + bias[col + 2]) * scale;
        v.w = (v.w + bias[col + 3]) * scale;
        uint32_t h01, l01, h23, l23;
        split2(v.x, v.y, h01, l01);
        split2(v.z, v.w, h23, l23);
        *(uint2*)(ph + obase + j * 4) = make_uint2(h01, h23);
        *(uint2*)(pl + obase + j * 4) = make_uint2(l01, l23);
    }
}

// K5: out projection
__global__ void __launch_bounds__(256, 2) out_wmma(const float* __restrict__ bias,
                                                   float* __restrict__ out) {
    extern __shared__ __align__(16) unsigned char dynsm[];
    __nv_bfloat16* sm = (__nv_bfloat16*)dynsm;
    uint32_t smb = smem_u32(dynsm);
    int tid = threadIdx.x;
    int wid = tid >> 5;
    int wy = wid & 3, wx = wid >> 2;
    int n0 = blockIdx.x * 64, m0 = blockIdx.y * 128;

    FragC acc[2][2];
    #pragma unroll
    for (int i = 0; i < 2; i++)
        #pragma unroll
        for (int j = 0; j < 2; j++) wmma::fill_fragment(acc[i][j], 0.0f);

    proj_body(m0, n0, acc, sm, smb, g_cthi, g_ctlo, g_wohi, g_wolo);

    float* stage = (float*)dynsm;
    #pragma unroll
    for (int i = 0; i < 2; i++)
        #pragma unroll
        for (int j = 0; j < 2; j++)
            wmma::store_matrix_sync(stage + (wy * 32 + i * 16) * 68 + wx * 32 + j * 16,
                                    acc[i][j], 68, wmma::mem_row_major);
    __syncthreads();

    int row = tid >> 1, half = (tid & 1) * 32;
    #pragma unroll
    for (int j = 0; j < 8; j++) {
        float4 v = *(float4*)&stage[row * 68 + half + j * 4];
        int col = n0 + half + j * 4;
        v.x += bias[col]; v.y += bias[col + 1]; v.z += bias[col + 2]; v.w += bias[col + 3];
        *(float4*)&out[(size_t)(m0 + row) * DD + col] = v;
    }
}

// ---------------------------------------------------------------------------
// K2: scores = Q.K^T. CTA 128(s) x 64(t), K=64 one-shot. smem 54KB, 2 CTAs/SM.
// ---------------------------------------------------------------------------
__global__ void __launch_bounds__(256, 2) scores_wmma() {
    extern __shared__ __align__(16) unsigned char dynsm[];
    __nv_bfloat16* sm = (__nv_bfloat16*)dynsm;
    uint32_t smb = smem_u32(dynsm);

    int tid = threadIdx.x;
    int wid = tid >> 5;
    int wy = wid & 3, wx = wid >> 2;
    int bh = blockIdx.z;
    int s0 = blockIdx.y * 128;
    int t0 = blockIdx.x * 64;

    #pragma unroll
    for (int l = 0; l < 4; l++) {
        int idx = tid + l * 256;
        int r = idx >> 3, c = idx & 7;
        size_t g = ((size_t)bh * SQ + s0 + r) * HDIM + c * 8;
        uint32_t d = smb + (r * STRD + c * 8) * 2;
        cpa16(d, &g_qhi[g]);
        cpa16(d + 9216 * 2, &g_qlo[g]);
    }
    #pragma unroll
    for (int l = 0; l < 2; l++) {
        int idx = tid + l * 256;
        int r = idx >> 3, c = idx & 7;
        size_t g = ((size_t)bh * SQ + t0 + r) * HDIM + c * 8;
        uint32_t d = smb + (18432 + r * STRD + c * 8) * 2;
        cpa16(d, &g_khi[g]);
        cpa16(d + 4608 * 2, &g_klo[g]);
    }
    CP_COMMIT;
    CP_WAIT0;
    __syncthreads();

    const __nv_bfloat16* Qh = sm;
    const __nv_bfloat16* Ql = sm + 9216;
    const __nv_bfloat16* Kh = sm + 18432;
    const __nv_bfloat16* Kl = sm + 23040;

    FragC acc[2][2];
    #pragma unroll
    for (int i = 0; i < 2; i++)
        #pragma unroll
        for (int j = 0; j < 2; j++) wmma::fill_fragment(acc[i][j], 0.0f);

    #pragma unroll
    for (int kk = 0; kk < 4; kk++) {
        FragA  ah[2], al[2];
        FragBc bh_[2], bl_[2];
        #pragma unroll
        for (int i = 0; i < 2; i++) {
            wmma::load_matrix_sync(ah[i], Qh + (wy * 32 + i * 16) * STRD + kk * 16, STRD);
            wmma::load_matrix_sync(al[i], Ql + (wy * 32 + i * 16) * STRD + kk * 16, STRD);
        }
        #pragma unroll
        for (int j = 0; j < 2; j++) {
            wmma::load_matrix_sync(bh_[j], Kh + (wx * 32 + j * 16) * STRD + kk * 16, STRD);
            wmma::load_matrix_sync(bl_[j], Kl + (wx * 32 + j * 16) * STRD + kk * 16, STRD);
        }
        #pragma unroll
        for (int i = 0; i < 2; i++)
            #pragma unroll
            for (int j = 0; j < 2; j++) {
                wmma::mma_sync(acc[i][j], ah[i], bh_[j], acc[i][j]);
                wmma::mma_sync(acc[i][j], ah[i], bl_[j], acc[i][j]);
                wmma::mma_sync(acc[i][j], al[i], bh_[j], acc[i][j]);
            }
    }
    #pragma unroll
    for (int i = 0; i < 2; i++)
        #pragma unroll
        for (int j = 0; j < 2; j++) {
            float* out = g_scores + ((size_t)bh * SQ + s0 + wy * 32 + i * 16) * SQ + t0 + wx * 32 + j * 16;
            wmma::store_matrix_sync(out, acc[i][j], SQ, wmma::mem_row_major);
        }
}

// ---------------------------------------------------------------------------
// K3: ctx = exp(scores) @ V. CTA 128(s) x 64(d); P single, V 2-stage. 72KB.
// ---------------------------------------------------------------------------
__global__ void __launch_bounds__(256, 2) ctx_wmma() {
    extern __shared__ __align__(16) unsigned char dynsm[];
    __nv_bfloat16* sm = (__nv_bfloat16*)dynsm;
    uint32_t smb = smem_u32(dynsm);

    int tid = threadIdx.x;
    int wid = tid >> 5;
    int wy = wid & 3, wx = wid >> 2;
    int bh = blockIdx.y;
    int s0 = blockIdx.x * 128;

    int row = tid >> 1, half = (tid & 1) * 32;
    const float* prow = g_scores + ((size_t)bh * SQ + s0 + row) * SQ + half;

    auto load_v = [&](int st, int c) {
        #pragma unroll
        for (int l = 0; l < 2; l++) {
            int idx = tid + l * 256;
            int r = idx >> 3, c8 = idx & 7;
            size_t g = ((size_t)bh * SQ + c * 64 + r) * HDIM + c8 * 8;
            uint32_t d = smb + (18432 + st * 9216 + r * STRD + c8 * 8) * 2;
            cpa16(d, &g_vhi[g]);
            cpa16(d + 4608 * 2, &g_vlo[g]);
        }
        CP_COMMIT;
    };

    FragC acc[2][2];
    #pragma unroll
    for (int i = 0; i < 2; i++)
        #pragma unroll
        for (int j = 0; j < 2; j++) wmma::fill_fragment(acc[i][j], 0.0f);

    float4 cur[8];
    #pragma unroll
    for (int j = 0; j < 8; j++) cur[j] = *(const float4*)&prow[j * 4];
    load_v(0, 0);

    __nv_bfloat16* Ph = sm;
    __nv_bfloat16* Pl = sm + 9216;

    float rowsum = 0.0f;
    for (int c = 0; c < 32; c++) {
        int st = c & 1;
        if (c + 1 < 32) load_v((c + 1) & 1, c + 1);
        #pragma unroll
        for (int j = 0; j < 8; j++) {
            float e0 = __expf(cur[j].x), e1 = __expf(cur[j].y);
            float e2 = __expf(cur[j].z), e3 = __expf(cur[j].w);
            rowsum += (e0 + e1) + (e2 + e3);
            uint32_t h01, l01, h23, l23;
            split2(e0, e1, h01, l01);
            split2(e2, e3, h23, l23);
            *(uint2*)&Ph[row * STRD + half + j * 4] = make_uint2(h01, h23);
            *(uint2*)&Pl[row * STRD + half + j * 4] = make_uint2(l01, l23);
        }
        if (c + 1 < 32) {
            #pragma unroll
            for (int j = 0; j < 8; j++) cur[j] = *(const float4*)&prow[(c + 1) * 64 + j * 4];
            CP_WAIT1;
        } else CP_WAIT0;
        __syncthreads();
        const __nv_bfloat16* Vh = sm + 18432 + st * 9216;
        const __nv_bfloat16* Vl = Vh + 4608;
        #pragma unroll
        for (int kk = 0; kk < 4; kk++) {
            FragA  ah[2], al[2];
            FragBr bh_[2], bl_[2];
            #pragma unroll
            for (int i = 0; i < 2; i++) {
                wmma::load_matrix_sync(ah[i], Ph + (wy * 32 + i * 16) * STRD + kk * 16, STRD);
                wmma::load_matrix_sync(al[i], Pl + (wy * 32 + i * 16) * STRD + kk * 16, STRD);
            }
            #pragma unroll
            for (int j = 0; j < 2; j++) {
                wmma::load_matrix_sync(bh_[j], Vh + (kk * 16) * STRD + wx * 32 + j * 16, STRD);
                wmma::load_matrix_sync(bl_[j], Vl + (kk * 16) * STRD + wx * 32 + j * 16, STRD);
            }
            #pragma unroll
            for (int i = 0; i < 2; i++)
                #pragma unroll
                for (int j = 0; j < 2; j++) {
                    wmma::mma_sync(acc[i][j], ah[i], bh_[j], acc[i][j]);
                    wmma::mma_sync(acc[i][j], ah[i], bl_[j], acc[i][j]);
                    wmma::mma_sync(acc[i][j], al[i], bh_[j], acc[i][j]);
                }
        }
        __syncthreads();
    }

    float tot = rowsum + __shfl_xor_sync(0xFFFFFFFFu, rowsum, 1);
    float inv = 1.0f / tot;
    if (!(tid & 1)) g_rowinv[(size_t)bh * SQ + s0 + row] = inv;

    float* stage = (float*)dynsm;   // 128 x 68
    __syncthreads();
    #pragma unroll
    for (int i = 0; i < 2; i++)
        #pragma unroll
        for (int j = 0; j < 2; j++)
            wmma::store_matrix_sync(stage + (wy * 32 + i * 16) * 68 + wx * 32 + j * 16,
                                    acc[i][j], 68, wmma::mem_row_major);
    __syncthreads();

    int b = bh >> 3, h = bh & 7;
    size_t obase = ((size_t)(s0 + row) * BB + b) * DD + h * HDIM + half;
    #pragma unroll
    for (int j = 0; j < 8; j++) {
        float4 v = *(float4*)&stage[row * 68 + half + j * 4];
        uint32_t h01, l01, h23, l23;
        split2(v.x * inv, v.y * inv, h01, l01);
        split2(v.z * inv, v.w * inv, h23, l23);
        *(uint2*)(g_cthi + obase + j * 4) = make_uint2(h01, h23);
        *(uint2*)(g_ctlo + obase + j * 4) = make_uint2(l01, l23);
    }
}

// ---------------------------------------------------------------------------
// K4: attn_weights = mean_h exp(scores) * rowinv  (float4 vectorized)
// ---------------------------------------------------------------------------
__global__ void head_avg(float* __restrict__ out_attn) {
    size_t i = (size_t)blockIdx.x * blockDim.x + threadIdx.x;
    size_t n4 = (size_t)BB * SQ * SQ / 4;
    if (i >= n4) return;
    size_t plane4 = (size_t)SQ * SQ / 4;
    size_t b    = i / plane4;
    size_t rem4 = i % plane4;
    size_t s    = rem4 / (SQ / 4);
    float4 sum = make_float4(0.f, 0.f, 0.f, 0.f);
    #pragma unroll
    for (int h = 0; h < HH; h++) {
        size_t bh = b * HH + h;
        float4 v = *((const float4*)(g_scores + bh * SQ * SQ) + rem4);
        float inv = g_rowinv[bh * SQ + s];
        sum.x += __expf(v.x) * inv;
        sum.y += __expf(v.y) * inv;
        sum.z += __expf(v.z) * inv;
        sum.w += __expf(v.w) * inv;
    }
    sum.x *= 0.125f; sum.y *= 0.125f; sum.z *= 0.125f; sum.w *= 0.125f;
    ((float4*)out_attn)[i] = sum;
}

extern "C" void kernel_launch(void* const* d_in, const int* in_sizes, int n_in,
                              void* d_out, int out_size) {
    const float* src   = (const float*)d_in[0];
    const float* in_w  = (const float*)d_in[1];
    const float* in_b  = (const float*)d_in[2];
    const float* out_w = (const float*)d_in[3];
    const float* out_b = (const float*)d_in[4];
    float* out      = (float*)d_out;
    float* attn_out = out + (size_t)SQ * BB * DD;

    __nv_bfloat16 *shi, *slo, *wihi, *wilo, *wohi, *wolo;
    cudaGetSymbolAddress((void**)&shi,  g_shi);
    cudaGetSymbolAddress((void**)&slo,  g_slo);
    cudaGetSymbolAddress((void**)&wihi, g_wihi);
    cudaGetSymbolAddress((void**)&wilo, g_wilo);
    cudaGetSymbolAddress((void**)&wohi, g_wohi);
    cudaGetSymbolAddress((void**)&wolo, g_wolo);

    const int SM_PROJ  = 27648 * 2;   // 55296 (single stage)
    const int SM_SCORE = 27648 * 2;   // 55296
    const int SM_CTX   = 36864 * 2;   // 73728
    cudaFuncSetAttribute(qkv_wmma,    cudaFuncAttributeMaxDynamicSharedMemorySize, SM_PROJ);
    cudaFuncSetAttribute(out_wmma,    cudaFuncAttributeMaxDynamicSharedMemorySize, SM_PROJ);
    cudaFuncSetAttribute(scores_wmma, cudaFuncAttributeMaxDynamicSharedMemorySize, SM_SCORE);
    cudaFuncSetAttribute(ctx_wmma,    cudaFuncAttributeMaxDynamicSharedMemorySize, SM_CTX);

    int n4s = MROWS * DD / 4, n4i = 3 * DD * DD / 4, n4o = DD * DD / 4;
    split_f32<<<(n4s + 255) / 256, 256>>>(src,  shi,  slo,  n4s);
    split_f32<<<(n4i + 255) / 256, 256>>>(in_w, wihi, wilo, n4i);
    split_f32<<<(n4o + 255) / 256, 256>>>(out_w, wohi, wolo, n4o);

    qkv_wmma<<<dim3(3 * DD / 64, MROWS / 128), 256, SM_PROJ>>>(in_b);
    scores_wmma<<<dim3(SQ / 64, SQ / 128, BH), 256, SM_SCORE>>>();
    ctx_wmma<<<dim3(SQ / 128, BH), 256, SM_CTX>>>();
    head_avg<<<(unsigned)(((size_t)BB * SQ * SQ / 4 + 255) / 256), 256>>>(attn_out);
    out_wmma<<<dim3(DD / 64, MROWS / 128), 256, SM_PROJ>>>(out_b, out);
}

// round 10
// speedup vs baseline: 1.5658x; 1.0555x over previous
#include <cuda_runtime.h>
#include <cuda_bf16.h>
#include <mma.h>
#include <cstdint>

using namespace nvcuda;

#define SQ   2048
#define BB   8
#define DD   512
#define HH   8
#define HDIM 64
#define MROWS (SQ*BB)       // 16384
#define BH    (BB*HH)       // 64
#define STRD 72             // 144B rows: conflict-free 8-row LDSM phases

// ---------------- scratch (__device__ globals) -----------------------------
__device__ __nv_bfloat16 g_shi[(size_t)MROWS*DD];
__device__ __nv_bfloat16 g_slo[(size_t)MROWS*DD];
__device__ __nv_bfloat16 g_wihi[(size_t)3*DD*DD];
__device__ __nv_bfloat16 g_wilo[(size_t)3*DD*DD];
__device__ __nv_bfloat16 g_wohi[(size_t)DD*DD];
__device__ __nv_bfloat16 g_wolo[(size_t)DD*DD];
__device__ __nv_bfloat16 g_qhi[(size_t)BH*SQ*HDIM];
__device__ __nv_bfloat16 g_qlo[(size_t)BH*SQ*HDIM];
__device__ __nv_bfloat16 g_khi[(size_t)BH*SQ*HDIM];
__device__ __nv_bfloat16 g_klo[(size_t)BH*SQ*HDIM];
__device__ __nv_bfloat16 g_vhi[(size_t)BH*SQ*HDIM];
__device__ __nv_bfloat16 g_vlo[(size_t)BH*SQ*HDIM];
__device__ float g_scores[(size_t)BH*SQ*SQ];
__device__ float g_rowinv[(size_t)BH*SQ];
__device__ __nv_bfloat16 g_cthi[(size_t)MROWS*DD];
__device__ __nv_bfloat16 g_ctlo[(size_t)MROWS*DD];

__device__ __forceinline__ void split2(float x0, float x1, uint32_t& hi, uint32_t& lo) {
    __nv_bfloat16 h0 = __float2bfloat16(x0), h1 = __float2bfloat16(x1);
    float r0 = x0 - __bfloat162float(h0), r1 = x1 - __bfloat162float(h1);
    __nv_bfloat162 H = __halves2bfloat162(h0, h1);
    __nv_bfloat162 L = __halves2bfloat162(__float2bfloat16(r0), __float2bfloat16(r1));
    hi = *(uint32_t*)&H;
    lo = *(uint32_t*)&L;
}
__device__ __forceinline__ uint32_t smem_u32(const void* p) {
    uint32_t a;
    asm("{ .reg .u64 t; cvta.to.shared.u64 t, %1; cvt.u32.u64 %0, t; }" : "=r"(a) : "l"(p));
    return a;
}
__device__ __forceinline__ void cpa16(uint32_t dst, const void* src) {
    asm volatile("cp.async.cg.shared.global [%0], [%1], 16;" :: "r"(dst), "l"(src));
}
#define CP_COMMIT asm volatile("cp.async.commit_group;" ::: "memory")
#define CP_WAIT0  asm volatile("cp.async.wait_group 0;" ::: "memory")
#define CP_WAIT1  asm volatile("cp.async.wait_group 1;" ::: "memory")

typedef wmma::fragment<wmma::matrix_a, 16, 16, 16, __nv_bfloat16, wmma::row_major> FragA;
typedef wmma::fragment<wmma::matrix_b, 16, 16, 16, __nv_bfloat16, wmma::col_major> FragBc;
typedef wmma::fragment<wmma::matrix_b, 16, 16, 16, __nv_bfloat16, wmma::row_major> FragBr;
typedef wmma::fragment<wmma::accumulator, 16, 16, 16, float> FragC;

// ---------------------------------------------------------------------------
// K0: elementwise fp32 -> split bf16
// ---------------------------------------------------------------------------
__global__ void split_f32(const float* __restrict__ in, __nv_bfloat16* __restrict__ hi,
                          __nv_bfloat16* __restrict__ lo, int n4) {
    int i = blockIdx.x * blockDim.x + threadIdx.x;
    if (i >= n4) return;
    float4 v = ((const float4*)in)[i];
    uint32_t h01, l01, h23, l23;
    split2(v.x, v.y, h01, l01);
    split2(v.z, v.w, h23, l23);
    ((uint2*)hi)[i] = make_uint2(h01, h23);
    ((uint2*)lo)[i] = make_uint2(l01, l23);
}

// ---------------------------------------------------------------------------
// Projection body: CTA 128(m) x 128(n), warp 32x64, K chunks of 64.
// smem: Ah 9216 | Al 9216 | Bh 9216 | Bl 9216 elems = 73728 B -> 2 CTAs/SM.
// ---------------------------------------------------------------------------
__device__ __forceinline__ void proj_body(int m0, int n0, FragC acc[2][4],
                                          __nv_bfloat16* sm, uint32_t smb,
                                          const __nv_bfloat16* gah, const __nv_bfloat16* gal,
                                          const __nv_bfloat16* gbh, const __nv_bfloat16* gbl) {
    int tid = threadIdx.x;
    int wid = tid >> 5;
    int wy = wid & 3, wx = wid >> 2;

    const __nv_bfloat16* Ah = sm;
    const __nv_bfloat16* Al = sm + 9216;
    const __nv_bfloat16* Bh = sm + 18432;
    const __nv_bfloat16* Bl = sm + 27648;

    for (int kt = 0; kt < 8; kt++) {
        int k0 = kt * 64;
        #pragma unroll
        for (int l = 0; l < 4; l++) {
            int idx = tid + l * 256;
            int r = idx >> 3, c = idx & 7;
            size_t ga = (size_t)(m0 + r) * DD + k0 + c * 8;
            size_t gb = (size_t)(n0 + r) * DD + k0 + c * 8;
            uint32_t d = smb + (r * STRD + c * 8) * 2;
            cpa16(d, &gah[ga]);
            cpa16(d + 9216 * 2, &gal[ga]);
            cpa16(d + 18432 * 2, &gbh[gb]);
            cpa16(d + 27648 * 2, &gbl[gb]);
        }
        CP_COMMIT;
        CP_WAIT0;
        __syncthreads();
        #pragma unroll
        for (int kk = 0; kk < 4; kk++) {
            FragA ah[2], al[2];
            #pragma unroll
            for (int i = 0; i < 2; i++) {
                wmma::load_matrix_sync(ah[i], Ah + (wy * 32 + i * 16) * STRD + kk * 16, STRD);
                wmma::load_matrix_sync(al[i], Al + (wy * 32 + i * 16) * STRD + kk * 16, STRD);
            }
            #pragma unroll
            for (int j = 0; j < 4; j++) {
                FragBc bh, bl;
                wmma::load_matrix_sync(bh, Bh + (wx * 64 + j * 16) * STRD + kk * 16, STRD);
                wmma::load_matrix_sync(bl, Bl + (wx * 64 + j * 16) * STRD + kk * 16, STRD);
                #pragma unroll
                for (int i = 0; i < 2; i++) {
                    wmma::mma_sync(acc[i][j], ah[i], bh, acc[i][j]);
                    wmma::mma_sync(acc[i][j], ah[i], bl, acc[i][j]);
                    wmma::mma_sync(acc[i][j], al[i], bh, acc[i][j]);
                }
            }
        }
        __syncthreads();
    }
}

// K1: QKV projection. CTA 128x128, scatters split q/k/v.
__global__ void __launch_bounds__(256, 2) qkv_wmma(const float* __restrict__ bias) {
    extern __shared__ __align__(16) unsigned char dynsm[];
    __nv_bfloat16* sm = (__nv_bfloat16*)dynsm;
    uint32_t smb = smem_u32(dynsm);
    int tid = threadIdx.x;
    int wid = tid >> 5;
    int wy = wid & 3, wx = wid >> 2;
    int n0 = blockIdx.x * 128, m0 = blockIdx.y * 128;

    FragC acc[2][4];
    #pragma unroll
    for (int i = 0; i < 2; i++)
        #pragma unroll
        for (int j = 0; j < 4; j++) wmma::fill_fragment(acc[i][j], 0.0f);

    proj_body(m0, n0, acc, sm, smb, g_shi, g_slo, g_wihi, g_wilo);

    float* stage = (float*)dynsm;    // 128 x 132
    #pragma unroll
    for (int i = 0; i < 2; i++)
        #pragma unroll
        for (int j = 0; j < 4; j++)
            wmma::store_matrix_sync(stage + (wy * 32 + i * 16) * 132 + wx * 64 + j * 16,
                                    acc[i][j], 132, wmma::mem_row_major);
    __syncthreads();

    int row = tid >> 1, half = (tid & 1) * 64;
    int colbase = n0 + half;              // 64-aligned -> one head, one part
    int part = colbase >> 9;
    int h = (colbase >> 6) & 7;
    int i = m0 + row;
    int s = i >> 3, b = i & 7;
    int bh = b * HH + h;
    float scale = (part == 0) ? 0.125f : 1.0f;
    size_t obase = ((size_t)bh * SQ + s) * HDIM;
    __nv_bfloat16* ph = (part == 0) ? g_qhi : (part == 1) ? g_khi : g_vhi;
    __nv_bfloat16* pl = (part == 0) ? g_qlo : (part == 1) ? g_klo : g_vlo;
    #pragma unroll
    for (int j = 0; j < 16; j++) {
        float4 v = *(float4*)&stage[row * 132 + half + j * 4];
        int col = colbase + j * 4;
        v.x = (v.x + bias[col]) * scale;
        v.y = (v.y + bias[col + 1]) * scale;
        v.z = (v.z + bias[col + 2]) * scale;
        v.w = (v.w + bias[col + 3]) * scale;
        uint32_t h01, l01, h23, l23;
        split2(v.x, v.y, h01, l01);
        split2(v.z, v.w, h23, l23);
        *(uint2*)(ph + obase + j * 4) = make_uint2(h01, h23);
        *(uint2*)(pl + obase + j * 4) = make_uint2(l01, l23);
    }
}

// K5: out projection. CTA 128x128.
__global__ void __launch_bounds__(256, 2) out_wmma(const float* __restrict__ bias,
                                                   float* __restrict__ out) {
    extern __shared__ __align__(16) unsigned char dynsm[];
    __nv_bfloat16* sm = (__nv_bfloat16*)dynsm;
    uint32_t smb = smem_u32(dynsm);
    int tid = threadIdx.x;
    int wid = tid >> 5;
    int wy = wid & 3, wx = wid >> 2;
    int n0 = blockIdx.x * 128, m0 = blockIdx.y * 128;

    FragC acc[2][4];
    #pragma unroll
    for (int i = 0; i < 2; i++)
        #pragma unroll
        for (int j = 0; j < 4; j++) wmma::fill_fragment(acc[i][j], 0.0f);

    proj_body(m0, n0, acc, sm, smb, g_cthi, g_ctlo, g_wohi, g_wolo);

    float* stage = (float*)dynsm;
    #pragma unroll
    for (int i = 0; i < 2; i++)
        #pragma unroll
        for (int j = 0; j < 4; j++)
            wmma::store_matrix_sync(stage + (wy * 32 + i * 16) * 132 + wx * 64 + j * 16,
                                    acc[i][j], 132, wmma::mem_row_major);
    __syncthreads();

    int row = tid >> 1, half = (tid & 1) * 64;
    int colbase = n0 + half;
    #pragma unroll
    for (int j = 0; j < 16; j++) {
        float4 v = *(float4*)&stage[row * 132 + half + j * 4];
        int col = colbase + j * 4;
        v.x += bias[col]; v.y += bias[col + 1]; v.z += bias[col + 2]; v.w += bias[col + 3];
        *(float4*)&out[(size_t)(m0 + row) * DD + col] = v;
    }
}

// ---------------------------------------------------------------------------
// K2: FUSED attention: S = Q.K^T (raw -> gmem), P = exp(S) (via L2 read-back),
// O += P.V ; rowsum fused. CTA = 128 s-rows x one bh, t swept in 64-chunks.
// smem (bf16 elems): Qh 0 | Ql 9216 | Ph 18432 | Pl 27648 | Kh 36864 |
//                    Kl 41472 | Vh 46080 | Vl 50688  -> 55296 elems = 108 KB.
// 2 CTAs/SM. K refilled right after S-MMA, V right after O-MMA (overlap).
// ---------------------------------------------------------------------------
__global__ void __launch_bounds__(256, 2) attn_fused() {
    extern __shared__ __align__(16) unsigned char dynsm[];
    __nv_bfloat16* sm = (__nv_bfloat16*)dynsm;
    uint32_t smb = smem_u32(dynsm);

    int tid = threadIdx.x;
    int wid = tid >> 5;
    int wy = wid & 3, wx = wid >> 2;
    int bh = blockIdx.y;
    int s0 = blockIdx.x * 128;
    int row = tid >> 1, half = (tid & 1) * 32;

    // Q tile (resident): 128 x 64 hi+lo
    #pragma unroll
    for (int l = 0; l < 4; l++) {
        int idx = tid + l * 256;
        int r = idx >> 3, c8 = idx & 7;
        size_t g = ((size_t)bh * SQ + s0 + r) * HDIM + c8 * 8;
        uint32_t d = smb + (r * STRD + c8 * 8) * 2;
        cpa16(d, &g_qhi[g]);
        cpa16(d + 9216 * 2, &g_qlo[g]);
    }
    CP_COMMIT;

    auto load_k = [&](int c) {
        #pragma unroll
        for (int l = 0; l < 2; l++) {
            int idx = tid + l * 256;
            int r = idx >> 3, c8 = idx & 7;
            size_t g = ((size_t)bh * SQ + c * 64 + r) * HDIM + c8 * 8;
            uint32_t d = smb + (36864 + r * STRD + c8 * 8) * 2;
            cpa16(d, &g_khi[g]);
            cpa16(d + 4608 * 2, &g_klo[g]);
        }
        CP_COMMIT;
    };
    auto load_v = [&](int c) {
        #pragma unroll
        for (int l = 0; l < 2; l++) {
            int idx = tid + l * 256;
            int r = idx >> 3, c8 = idx & 7;
            size_t g = ((size_t)bh * SQ + c * 64 + r) * HDIM + c8 * 8;
            uint32_t d = smb + (46080 + r * STRD + c8 * 8) * 2;
            cpa16(d, &g_vhi[g]);
            cpa16(d + 4608 * 2, &g_vlo[g]);
        }
        CP_COMMIT;
    };
    load_k(0);
    load_v(0);

    const __nv_bfloat16* Qh = sm;
    const __nv_bfloat16* Ql = sm + 9216;
    __nv_bfloat16* Ph = sm + 18432;
    __nv_bfloat16* Pl = sm + 27648;
    const __nv_bfloat16* Kh = sm + 36864;
    const __nv_bfloat16* Kl = sm + 41472;
    const __nv_bfloat16* Vh = sm + 46080;
    const __nv_bfloat16* Vl = sm + 50688;

    FragC accO[2][2];
    #pragma unroll
    for (int i = 0; i < 2; i++)
        #pragma unroll
        for (int j = 0; j < 2; j++) wmma::fill_fragment(accO[i][j], 0.0f);

    float rowsum = 0.0f;

    for (int c = 0; c < 32; c++) {
        CP_WAIT1;                 // K[c] (and Q on c==0) arrived
        __syncthreads();

        // ---- S = Q.K^T (3-product) ----
        FragC accS[2][2];
        #pragma unroll
        for (int i = 0; i < 2; i++)
            #pragma unroll
            for (int j = 0; j < 2; j++) wmma::fill_fragment(accS[i][j], 0.0f);
        #pragma unroll
        for (int kk = 0; kk < 4; kk++) {
            FragA ah[2], al[2];
            #pragma unroll
            for (int i = 0; i < 2; i++) {
                wmma::load_matrix_sync(ah[i], Qh + (wy * 32 + i * 16) * STRD + kk * 16, STRD);
                wmma::load_matrix_sync(al[i], Ql + (wy * 32 + i * 16) * STRD + kk * 16, STRD);
            }
            #pragma unroll
            for (int j = 0; j < 2; j++) {
                FragBc bh_, bl_;
                wmma::load_matrix_sync(bh_, Kh + (wx * 32 + j * 16) * STRD + kk * 16, STRD);
                wmma::load_matrix_sync(bl_, Kl + (wx * 32 + j * 16) * STRD + kk * 16, STRD);
                #pragma unroll
                for (int i = 0; i < 2; i++) {
                    wmma::mma_sync(accS[i][j], ah[i], bh_, accS[i][j]);
                    wmma::mma_sync(accS[i][j], ah[i], bl_, accS[i][j]);
                    wmma::mma_sync(accS[i][j], al[i], bh_, accS[i][j]);
                }
            }
        }
        // raw S straight to gmem (head_avg consumes it later)
        #pragma unroll
        for (int i = 0; i < 2; i++)
            #pragma unroll
            for (int j = 0; j < 2; j++) {
                float* sp = g_scores + ((size_t)bh * SQ + s0 + wy * 32 + i * 16) * SQ
                          + c * 64 + wx * 32 + j * 16;
                wmma::store_matrix_sync(sp, accS[i][j], SQ, wmma::mem_row_major);
            }
        __syncthreads();          // S-MMA + stores done; K buffer free
        if (c + 1 < 32) load_k(c + 1);

        // ---- read back S (L2 hit), exp, rowsum, split -> Ph/Pl ----
        const float* srow = g_scores + ((size_t)bh * SQ + s0 + row) * SQ + c * 64 + half;
        #pragma unroll
        for (int j = 0; j < 8; j++) {
            float4 v = *(const float4*)&srow[j * 4];
            float e0 = __expf(v.x), e1 = __expf(v.y);
            float e2 = __expf(v.z), e3 = __expf(v.w);
            rowsum += (e0 + e1) + (e2 + e3);
            uint32_t h01, l01, h23, l23;
            split2(e0, e1, h01, l01);
            split2(e2, e3, h23, l23);
            *(uint2*)&Ph[row * STRD + half + j * 4] = make_uint2(h01, h23);
            *(uint2*)&Pl[row * STRD + half + j * 4] = make_uint2(l01, l23);
        }
        if (c + 1 < 32) CP_WAIT1; else CP_WAIT0;   // V[c] arrived
        __syncthreads();          // Ph/Pl visible + V ready

        // ---- O += P.V (3-product) ----
        #pragma unroll
        for (int kk = 0; kk < 4; kk++) {
            FragA ah[2], al[2];
            #pragma unroll
            for (int i = 0; i < 2; i++) {
                wmma::load_matrix_sync(ah[i], Ph + (wy * 32 + i * 16) * STRD + kk * 16, STRD);
                wmma::load_matrix_sync(al[i], Pl + (wy * 32 + i * 16) * STRD + kk * 16, STRD);
            }
            #pragma unroll
            for (int j = 0; j < 2; j++) {
                FragBr bh_, bl_;
                wmma::load_matrix_sync(bh_, Vh + (kk * 16) * STRD + wx * 32 + j * 16, STRD);
                wmma::load_matrix_sync(bl_, Vl + (kk * 16) * STRD + wx * 32 + j * 16, STRD);
                #pragma unroll
                for (int i = 0; i < 2; i++) {
                    wmma::mma_sync(accO[i][j], ah[i], bh_, accO[i][j]);
                    wmma::mma_sync(accO[i][j], ah[i], bl_, accO[i][j]);
                    wmma::mma_sync(accO[i][j], al[i], bh_, accO[i][j]);
                }
            }
        }
        __syncthreads();          // O-MMA done; V buffer free
        if (c + 1 < 32) load_v(c + 1);
    }

    // ---- epilogue: rowinv + normalized split ctx ----
    float tot = rowsum + __shfl_xor_sync(0xFFFFFFFFu, rowsum, 1);
    float inv = 1.0f / tot;
    if (!(tid & 1)) g_rowinv[(size_t)bh * SQ + s0 + row] = inv;

    float* stage = (float*)(sm + 18432);   // alias P region (O-MMA done + synced)
    #pragma unroll
    for (int i = 0; i < 2; i++)
        #pragma unroll
        for (int j = 0; j < 2; j++)
            wmma::store_matrix_sync(stage + (wy * 32 + i * 16) * 68 + wx * 32 + j * 16,
                                    accO[i][j], 68, wmma::mem_row_major);
    __syncthreads();

    int b = bh >> 3, h = bh & 7;
    size_t obase = ((size_t)(s0 + row) * BB + b) * DD + h * HDIM + half;
    #pragma unroll
    for (int j = 0; j < 8; j++) {
        float4 v = *(float4*)&stage[row * 68 + half + j * 4];
        uint32_t h01, l01, h23, l23;
        split2(v.x * inv, v.y * inv, h01, l01);
        split2(v.z * inv, v.w * inv, h23, l23);
        *(uint2*)(g_cthi + obase + j * 4) = make_uint2(h01, h23);
        *(uint2*)(g_ctlo + obase + j * 4) = make_uint2(l01, l23);
    }
}

// ---------------------------------------------------------------------------
// K4: attn_weights = mean_h exp(scores) * rowinv  (float4 vectorized)
// ---------------------------------------------------------------------------
__global__ void head_avg(float* __restrict__ out_attn) {
    size_t i = (size_t)blockIdx.x * blockDim.x + threadIdx.x;
    size_t n4 = (size_t)BB * SQ * SQ / 4;
    if (i >= n4) return;
    size_t plane4 = (size_t)SQ * SQ / 4;
    size_t b    = i / plane4;
    size_t rem4 = i % plane4;
    size_t s    = rem4 / (SQ / 4);
    float4 sum = make_float4(0.f, 0.f, 0.f, 0.f);
    #pragma unroll
    for (int h = 0; h < HH; h++) {
        size_t bh = b * HH + h;
        float4 v = *((const float4*)(g_scores + bh * SQ * SQ) + rem4);
        float inv = g_rowinv[bh * SQ + s];
        sum.x += __expf(v.x) * inv;
        sum.y += __expf(v.y) * inv;
        sum.z += __expf(v.z) * inv;
        sum.w += __expf(v.w) * inv;
    }
    sum.x *= 0.125f; sum.y *= 0.125f; sum.z *= 0.125f; sum.w *= 0.125f;
    ((float4*)out_attn)[i] = sum;
}

extern "C" void kernel_launch(void* const* d_in, const int* in_sizes, int n_in,
                              void* d_out, int out_size) {
    const float* src   = (const float*)d_in[0];
    const float* in_w  = (const float*)d_in[1];
    const float* in_b  = (const float*)d_in[2];
    const float* out_w = (const float*)d_in[3];
    const float* out_b = (const float*)d_in[4];
    float* out      = (float*)d_out;
    float* attn_out = out + (size_t)SQ * BB * DD;

    __nv_bfloat16 *shi, *slo, *wihi, *wilo, *wohi, *wolo;
    cudaGetSymbolAddress((void**)&shi,  g_shi);
    cudaGetSymbolAddress((void**)&slo,  g_slo);
    cudaGetSymbolAddress((void**)&wihi, g_wihi);
    cudaGetSymbolAddress((void**)&wilo, g_wilo);
    cudaGetSymbolAddress((void**)&wohi, g_wohi);
    cudaGetSymbolAddress((void**)&wolo, g_wolo);

    const int SM_PROJ = 36864 * 2;   // 73728 B
    const int SM_ATTN = 55296 * 2;   // 110592 B
    cudaFuncSetAttribute(qkv_wmma,   cudaFuncAttributeMaxDynamicSharedMemorySize, SM_PROJ);
    cudaFuncSetAttribute(out_wmma,   cudaFuncAttributeMaxDynamicSharedMemorySize, SM_PROJ);
    cudaFuncSetAttribute(attn_fused, cudaFuncAttributeMaxDynamicSharedMemorySize, SM_ATTN);

    int n4s = MROWS * DD / 4, n4i = 3 * DD * DD / 4, n4o = DD * DD / 4;
    split_f32<<<(n4s + 255) / 256, 256>>>(src,  shi,  slo,  n4s);
    split_f32<<<(n4i + 255) / 256, 256>>>(in_w, wihi, wilo, n4i);
    split_f32<<<(n4o + 255) / 256, 256>>>(out_w, wohi, wolo, n4o);

    qkv_wmma<<<dim3(3 * DD / 128, MROWS / 128), 256, SM_PROJ>>>(in_b);
    attn_fused<<<dim3(SQ / 128, BH), 256, SM_ATTN>>>();
    head_avg<<<(unsigned)(((size_t)BB * SQ * SQ / 4 + 255) / 256), 256>>>(attn_out);
    out_wmma<<<dim3(DD / 128, MROWS / 128), 256, SM_PROJ>>>(out_b, out);
}

// round 11
// speedup vs baseline: 1.6389x; 1.0467x over previous
#include <cuda_runtime.h>
#include <cuda_bf16.h>
#include <mma.h>
#include <cstdint>

using namespace nvcuda;

#define SQ   2048
#define BB   8
#define DD   512
#define HH   8
#define HDIM 64
#define MROWS (SQ*BB)       // 16384
#define BH    (BB*HH)       // 64
#define STRD 72             // 144B rows: conflict-free 8-row LDSM phases

// ---------------- scratch (__device__ globals) -----------------------------
__device__ __nv_bfloat16 g_shi[(size_t)MROWS*DD];
__device__ __nv_bfloat16 g_slo[(size_t)MROWS*DD];
__device__ __nv_bfloat16 g_wihi[(size_t)3*DD*DD];
__device__ __nv_bfloat16 g_wilo[(size_t)3*DD*DD];
__device__ __nv_bfloat16 g_wohi[(size_t)DD*DD];
__device__ __nv_bfloat16 g_wolo[(size_t)DD*DD];
__device__ __nv_bfloat16 g_qhi[(size_t)BH*SQ*HDIM];
__device__ __nv_bfloat16 g_qlo[(size_t)BH*SQ*HDIM];
__device__ __nv_bfloat16 g_khi[(size_t)BH*SQ*HDIM];
__device__ __nv_bfloat16 g_klo[(size_t)BH*SQ*HDIM];
__device__ __nv_bfloat16 g_vhi[(size_t)BH*SQ*HDIM];
__device__ __nv_bfloat16 g_vlo[(size_t)BH*SQ*HDIM];
__device__ float g_scores[(size_t)BH*SQ*SQ];
__device__ float g_rowinv[(size_t)BH*SQ];
__device__ __nv_bfloat16 g_cthi[(size_t)MROWS*DD];
__device__ __nv_bfloat16 g_ctlo[(size_t)MROWS*DD];

__device__ __forceinline__ void split2(float x0, float x1, uint32_t& hi, uint32_t& lo) {
    __nv_bfloat16 h0 = __float2bfloat16(x0), h1 = __float2bfloat16(x1);
    float r0 = x0 - __bfloat162float(h0), r1 = x1 - __bfloat162float(h1);
    __nv_bfloat162 H = __halves2bfloat162(h0, h1);
    __nv_bfloat162 L = __halves2bfloat162(__float2bfloat16(r0), __float2bfloat16(r1));
    hi = *(uint32_t*)&H;
    lo = *(uint32_t*)&L;
}
__device__ __forceinline__ uint32_t smem_u32(const void* p) {
    uint32_t a;
    asm("{ .reg .u64 t; cvta.to.shared.u64 t, %1; cvt.u32.u64 %0, t; }" : "=r"(a) : "l"(p));
    return a;
}
__device__ __forceinline__ void cpa16(uint32_t dst, const void* src) {
    asm volatile("cp.async.cg.shared.global [%0], [%1], 16;" :: "r"(dst), "l"(src));
}
#define CP_COMMIT asm volatile("cp.async.commit_group;" ::: "memory")
#define CP_WAIT0  asm volatile("cp.async.wait_group 0;" ::: "memory")
#define CP_WAIT1  asm volatile("cp.async.wait_group 1;" ::: "memory")

typedef wmma::fragment<wmma::matrix_a, 16, 16, 16, __nv_bfloat16, wmma::row_major> FragA;
typedef wmma::fragment<wmma::matrix_b, 16, 16, 16, __nv_bfloat16, wmma::col_major> FragBc;
typedef wmma::fragment<wmma::matrix_b, 16, 16, 16, __nv_bfloat16, wmma::row_major> FragBr;
typedef wmma::fragment<wmma::accumulator, 16, 16, 16, float> FragC;

// ---------------------------------------------------------------------------
// K0: elementwise fp32 -> split bf16
// ---------------------------------------------------------------------------
__global__ void split_f32(const float* __restrict__ in, __nv_bfloat16* __restrict__ hi,
                          __nv_bfloat16* __restrict__ lo, int n4) {
    int i = blockIdx.x * blockDim.x + threadIdx.x;
    if (i >= n4) return;
    float4 v = ((const float4*)in)[i];
    uint32_t h01, l01, h23, l23;
    split2(v.x, v.y, h01, l01);
    split2(v.z, v.w, h23, l23);
    ((uint2*)hi)[i] = make_uint2(h01, h23);
    ((uint2*)lo)[i] = make_uint2(l01, l23);
}

// ---------------------------------------------------------------------------
// Projection body: CTA 128(m) x 128(n), warp 32x64, K chunks of 64.
// MMAs ordered product-outermost (reuse distance 4) on j-pairs.
// smem: Ah 9216 | Al 9216 | Bh 9216 | Bl 9216 elems = 73728 B -> 2 CTAs/SM.
// ---------------------------------------------------------------------------
__device__ __forceinline__ void proj_body(int m0, int n0, FragC acc[2][4],
                                          __nv_bfloat16* sm, uint32_t smb,
                                          const __nv_bfloat16* gah, const __nv_bfloat16* gal,
                                          const __nv_bfloat16* gbh, const __nv_bfloat16* gbl) {
    int tid = threadIdx.x;
    int wid = tid >> 5;
    int wy = wid & 3, wx = wid >> 2;

    const __nv_bfloat16* Ah = sm;
    const __nv_bfloat16* Al = sm + 9216;
    const __nv_bfloat16* Bh = sm + 18432;
    const __nv_bfloat16* Bl = sm + 27648;

    for (int kt = 0; kt < 8; kt++) {
        int k0 = kt * 64;
        #pragma unroll
        for (int l = 0; l < 4; l++) {
            int idx = tid + l * 256;
            int r = idx >> 3, c = idx & 7;
            size_t ga = (size_t)(m0 + r) * DD + k0 + c * 8;
            size_t gb = (size_t)(n0 + r) * DD + k0 + c * 8;
            uint32_t d = smb + (r * STRD + c * 8) * 2;
            cpa16(d, &gah[ga]);
            cpa16(d + 9216 * 2, &gal[ga]);
            cpa16(d + 18432 * 2, &gbh[gb]);
            cpa16(d + 27648 * 2, &gbl[gb]);
        }
        CP_COMMIT;
        CP_WAIT0;
        __syncthreads();
        #pragma unroll
        for (int kk = 0; kk < 4; kk++) {
            FragA ah[2], al[2];
            #pragma unroll
            for (int i = 0; i < 2; i++) {
                wmma::load_matrix_sync(ah[i], Ah + (wy * 32 + i * 16) * STRD + kk * 16, STRD);
                wmma::load_matrix_sync(al[i], Al + (wy * 32 + i * 16) * STRD + kk * 16, STRD);
            }
            #pragma unroll
            for (int jp = 0; jp < 2; jp++) {
                FragBc bh[2], bl[2];
                #pragma unroll
                for (int jj = 0; jj < 2; jj++) {
                    int j = jp * 2 + jj;
                    wmma::load_matrix_sync(bh[jj], Bh + (wx * 64 + j * 16) * STRD + kk * 16, STRD);
                    wmma::load_matrix_sync(bl[jj], Bl + (wx * 64 + j * 16) * STRD + kk * 16, STRD);
                }
                // product-outermost: same-acc reuse distance = 4
                #pragma unroll
                for (int jj = 0; jj < 2; jj++)
                    #pragma unroll
                    for (int i = 0; i < 2; i++)
                        wmma::mma_sync(acc[i][jp * 2 + jj], ah[i], bh[jj], acc[i][jp * 2 + jj]);
                #pragma unroll
                for (int jj = 0; jj < 2; jj++)
                    #pragma unroll
                    for (int i = 0; i < 2; i++)
                        wmma::mma_sync(acc[i][jp * 2 + jj], ah[i], bl[jj], acc[i][jp * 2 + jj]);
                #pragma unroll
                for (int jj = 0; jj < 2; jj++)
                    #pragma unroll
                    for (int i = 0; i < 2; i++)
                        wmma::mma_sync(acc[i][jp * 2 + jj], al[i], bh[jj], acc[i][jp * 2 + jj]);
            }
        }
        __syncthreads();
    }
}

// K1: QKV projection. CTA 128x128, scatters split q/k/v.
__global__ void __launch_bounds__(256, 2) qkv_wmma(const float* __restrict__ bias) {
    extern __shared__ __align__(16) unsigned char dynsm[];
    __nv_bfloat16* sm = (__nv_bfloat16*)dynsm;
    uint32_t smb = smem_u32(dynsm);
    int tid = threadIdx.x;
    int wid = tid >> 5;
    int wy = wid & 3, wx = wid >> 2;
    int n0 = blockIdx.x * 128, m0 = blockIdx.y * 128;

    FragC acc[2][4];
    #pragma unroll
    for (int i = 0; i < 2; i++)
        #pragma unroll
        for (int j = 0; j < 4; j++) wmma::fill_fragment(acc[i][j], 0.0f);

    proj_body(m0, n0, acc, sm, smb, g_shi, g_slo, g_wihi, g_wilo);

    float* stage = (float*)dynsm;    // 128 x 132
    #pragma unroll
    for (int i = 0; i < 2; i++)
        #pragma unroll
        for (int j = 0; j < 4; j++)
            wmma::store_matrix_sync(stage + (wy * 32 + i * 16) * 132 + wx * 64 + j * 16,
                                    acc[i][j], 132, wmma::mem_row_major);
    __syncthreads();

    int row = tid >> 1, half = (tid & 1) * 64;
    int colbase = n0 + half;              // 64-aligned -> one head, one part
    int part = colbase >> 9;
    int h = (colbase >> 6) & 7;
    int i = m0 + row;
    int s = i >> 3, b = i & 7;
    int bh = b * HH + h;
    float scale = (part == 0) ? 0.125f : 1.0f;
    size_t obase = ((size_t)bh * SQ + s) * HDIM;
    __nv_bfloat16* ph = (part == 0) ? g_qhi : (part == 1) ? g_khi : g_vhi;
    __nv_bfloat16* pl = (part == 0) ? g_qlo : (part == 1) ? g_klo : g_vlo;
    #pragma unroll
    for (int j = 0; j < 16; j++) {
        float4 v = *(float4*)&stage[row * 132 + half + j * 4];
        int col = colbase + j * 4;
        v.x = (v.x + bias[col]) * scale;
        v.y = (v.y + bias[col + 1]) * scale;
        v.z = (v.z + bias[col + 2]) * scale;
        v.w = (v.w + bias[col + 3]) * scale;
        uint32_t h01, l01, h23, l23;
        split2(v.x, v.y, h01, l01);
        split2(v.z, v.w, h23, l23);
        *(uint2*)(ph + obase + j * 4) = make_uint2(h01, h23);
        *(uint2*)(pl + obase + j * 4) = make_uint2(l01, l23);
    }
}

// K5: out projection. CTA 128x128.
__global__ void __launch_bounds__(256, 2) out_wmma(const float* __restrict__ bias,
                                                   float* __restrict__ out) {
    extern __shared__ __align__(16) unsigned char dynsm[];
    __nv_bfloat16* sm = (__nv_bfloat16*)dynsm;
    uint32_t smb = smem_u32(dynsm);
    int tid = threadIdx.x;
    int wid = tid >> 5;
    int wy = wid & 3, wx = wid >> 2;
    int n0 = blockIdx.x * 128, m0 = blockIdx.y * 128;

    FragC acc[2][4];
    #pragma unroll
    for (int i = 0; i < 2; i++)
        #pragma unroll
        for (int j = 0; j < 4; j++) wmma::fill_fragment(acc[i][j], 0.0f);

    proj_body(m0, n0, acc, sm, smb, g_cthi, g_ctlo, g_wohi, g_wolo);

    float* stage = (float*)dynsm;
    #pragma unroll
    for (int i = 0; i < 2; i++)
        #pragma unroll
        for (int j = 0; j < 4; j++)
            wmma::store_matrix_sync(stage + (wy * 32 + i * 16) * 132 + wx * 64 + j * 16,
                                    acc[i][j], 132, wmma::mem_row_major);
    __syncthreads();

    int row = tid >> 1, half = (tid & 1) * 64;
    int colbase = n0 + half;
    #pragma unroll
    for (int j = 0; j < 16; j++) {
        float4 v = *(float4*)&stage[row * 132 + half + j * 4];
        int col = colbase + j * 4;
        v.x += bias[col]; v.y += bias[col + 1]; v.z += bias[col + 2]; v.w += bias[col + 3];
        *(float4*)&out[(size_t)(m0 + row) * DD + col] = v;
    }
}

// ---------------------------------------------------------------------------
// K2: FUSED attention. S-MMA -> (gmem raw + smem f32 stage) -> exp/rowsum/
// split (all smem) -> O-MMA. CTA = 128 s-rows x one bh, 64-wide t chunks.
// smem (bf16 elems): Qh 0 | Ql 9216 | Ph 18432 | Pl 27648 | Kh 36864 |
//                    Kl 41472 | Vh 46080 | Vl 50688  -> 55296 elems = 108 KB.
// f32 S-stage (128x68 = 34816B) aliases the Ph/Pl region (36864B).
// ---------------------------------------------------------------------------
__global__ void __launch_bounds__(256, 2) attn_fused() {
    extern __shared__ __align__(16) unsigned char dynsm[];
    __nv_bfloat16* sm = (__nv_bfloat16*)dynsm;
    uint32_t smb = smem_u32(dynsm);

    int tid = threadIdx.x;
    int wid = tid >> 5;
    int wy = wid & 3, wx = wid >> 2;
    int bh = blockIdx.y;
    int s0 = blockIdx.x * 128;
    int row = tid >> 1, half = (tid & 1) * 32;

    // Q tile (resident): 128 x 64 hi+lo
    #pragma unroll
    for (int l = 0; l < 4; l++) {
        int idx = tid + l * 256;
        int r = idx >> 3, c8 = idx & 7;
        size_t g = ((size_t)bh * SQ + s0 + r) * HDIM + c8 * 8;
        uint32_t d = smb + (r * STRD + c8 * 8) * 2;
        cpa16(d, &g_qhi[g]);
        cpa16(d + 9216 * 2, &g_qlo[g]);
    }
    CP_COMMIT;

    auto load_k = [&](int c) {
        #pragma unroll
        for (int l = 0; l < 2; l++) {
            int idx = tid + l * 256;
            int r = idx >> 3, c8 = idx & 7;
            size_t g = ((size_t)bh * SQ + c * 64 + r) * HDIM + c8 * 8;
            uint32_t d = smb + (36864 + r * STRD + c8 * 8) * 2;
            cpa16(d, &g_khi[g]);
            cpa16(d + 4608 * 2, &g_klo[g]);
        }
        CP_COMMIT;
    };
    auto load_v = [&](int c) {
        #pragma unroll
        for (int l = 0; l < 2; l++) {
            int idx = tid + l * 256;
            int r = idx >> 3, c8 = idx & 7;
            size_t g = ((size_t)bh * SQ + c * 64 + r) * HDIM + c8 * 8;
            uint32_t d = smb + (46080 + r * STRD + c8 * 8) * 2;
            cpa16(d, &g_vhi[g]);
            cpa16(d + 4608 * 2, &g_vlo[g]);
        }
        CP_COMMIT;
    };
    load_k(0);
    load_v(0);

    const __nv_bfloat16* Qh = sm;
    const __nv_bfloat16* Ql = sm + 9216;
    __nv_bfloat16* Ph = sm + 18432;
    __nv_bfloat16* Pl = sm + 27648;
    float* sstage = (float*)(sm + 18432);   // aliases Ph/Pl, 128 x 68 f32
    const __nv_bfloat16* Kh = sm + 36864;
    const __nv_bfloat16* Kl = sm + 41472;
    const __nv_bfloat16* Vh = sm + 46080;
    const __nv_bfloat16* Vl = sm + 50688;

    FragC accO[2][2];
    #pragma unroll
    for (int i = 0; i < 2; i++)
        #pragma unroll
        for (int j = 0; j < 2; j++) wmma::fill_fragment(accO[i][j], 0.0f);

    float rowsum = 0.0f;

    for (int c = 0; c < 32; c++) {
        CP_WAIT1;                 // K[c] (and Q on c==0) arrived
        __syncthreads();          // also: Ph/Pl consumed by previous O-MMA

        // ---- S = Q.K^T (3-product, product-outermost ordering) ----
        FragC accS[2][2];
        #pragma unroll
        for (int i = 0; i < 2; i++)
            #pragma unroll
            for (int j = 0; j < 2; j++) wmma::fill_fragment(accS[i][j], 0.0f);
        #pragma unroll
        for (int kk = 0; kk < 4; kk++) {
            FragA ah[2], al[2];
            FragBc bh_[2], bl_[2];
            #pragma unroll
            for (int i = 0; i < 2; i++) {
                wmma::load_matrix_sync(ah[i], Qh + (wy * 32 + i * 16) * STRD + kk * 16, STRD);
                wmma::load_matrix_sync(al[i], Ql + (wy * 32 + i * 16) * STRD + kk * 16, STRD);
            }
            #pragma unroll
            for (int j = 0; j < 2; j++) {
                wmma::load_matrix_sync(bh_[j], Kh + (wx * 32 + j * 16) * STRD + kk * 16, STRD);
                wmma::load_matrix_sync(bl_[j], Kl + (wx * 32 + j * 16) * STRD + kk * 16, STRD);
            }
            #pragma unroll
            for (int j = 0; j < 2; j++)
                #pragma unroll
                for (int i = 0; i < 2; i++)
                    wmma::mma_sync(accS[i][j], ah[i], bh_[j], accS[i][j]);
            #pragma unroll
            for (int j = 0; j < 2; j++)
                #pragma unroll
                for (int i = 0; i < 2; i++)
                    wmma::mma_sync(accS[i][j], ah[i], bl_[j], accS[i][j]);
            #pragma unroll
            for (int j = 0; j < 2; j++)
                #pragma unroll
                for (int i = 0; i < 2; i++)
                    wmma::mma_sync(accS[i][j], al[i], bh_[j], accS[i][j]);
        }
        // raw S to gmem (head_avg consumes later) + f32 smem stage (exp path)
        #pragma unroll
        for (int i = 0; i < 2; i++)
            #pragma unroll
            for (int j = 0; j < 2; j++) {
                float* sp = g_scores + ((size_t)bh * SQ + s0 + wy * 32 + i * 16) * SQ
                          + c * 64 + wx * 32 + j * 16;
                wmma::store_matrix_sync(sp, accS[i][j], SQ, wmma::mem_row_major);
                wmma::store_matrix_sync(sstage + (wy * 32 + i * 16) * 68 + wx * 32 + j * 16,
                                        accS[i][j], 68, wmma::mem_row_major);
            }
        __syncthreads();          // stage visible; K buffer free
        if (c + 1 < 32) load_k(c + 1);

        // ---- exp + rowsum from smem stage into regs ----
        uint32_t ph_r[8], pl_r[8];
        #pragma unroll
        for (int j = 0; j < 8; j++) {
            float4 v = *(const float4*)&sstage[row * 68 + half + j * 4];
            float e0 = __expf(v.x), e1 = __expf(v.y);
            float e2 = __expf(v.z), e3 = __expf(v.w);
            rowsum += (e0 + e1) + (e2 + e3);
            uint32_t h01, l01, h23, l23;
            split2(e0, e1, h01, l01);
            split2(e2, e3, h23, l23);
            ph_r[j] = 0; pl_r[j] = 0;   // placeholder to keep arrays live
            ph_r[j] = h01; pl_r[j] = l01;
            // pack pairs: store immediately after barrier below
            ((uint2*)ph_r)[j & 3] = make_uint2(h01, h23);   // overwritten pattern avoided below
        }
        // NOTE: simpler correct path: recompute writes after barrier from saved float4s
        // (re-read stage is raced after barrier, so save exp values in regs instead)
        float e_save[32];
        #pragma unroll
        for (int j = 0; j < 8; j++) {
            float4 v = *(const float4*)&sstage[row * 68 + half + j * 4];
            e_save[4 * j]     = __expf(v.x);
            e_save[4 * j + 1] = __expf(v.y);
            e_save[4 * j + 2] = __expf(v.z);
            e_save[4 * j + 3] = __expf(v.w);
        }
        __syncthreads();          // all stage reads done -> safe to write Ph/Pl
        #pragma unroll
        for (int j = 0; j < 8; j++) {
            uint32_t h01, l01, h23, l23;
            split2(e_save[4 * j], e_save[4 * j + 1], h01, l01);
            split2(e_save[4 * j + 2], e_save[4 * j + 3], h23, l23);
            *(uint2*)&Ph[row * STRD + half + j * 4] = make_uint2(h01, h23);
            *(uint2*)&Pl[row * STRD + half + j * 4] = make_uint2(l01, l23);
        }
        if (c + 1 < 32) CP_WAIT1; else CP_WAIT0;   // V[c] arrived
        __syncthreads();          // Ph/Pl visible + V ready

        // ---- O += P.V (3-product, product-outermost) ----
        #pragma unroll
        for (int kk = 0; kk < 4; kk++) {
            FragA ah[2], al[2];
            FragBr bh_[2], bl_[2];
            #pragma unroll
            for (int i = 0; i < 2; i++) {
                wmma::load_matrix_sync(ah[i], Ph + (wy * 32 + i * 16) * STRD + kk * 16, STRD);
                wmma::load_matrix_sync(al[i], Pl + (wy * 32 + i * 16) * STRD + kk * 16, STRD);
            }
            #pragma unroll
            for (int j = 0; j < 2; j++) {
                wmma::load_matrix_sync(bh_[j], Vh + (kk * 16) * STRD + wx * 32 + j * 16, STRD);
                wmma::load_matrix_sync(bl_[j], Vl + (kk * 16) * STRD + wx * 32 + j * 16, STRD);
            }
            #pragma unroll
            for (int j = 0; j < 2; j++)
                #pragma unroll
                for (int i = 0; i < 2; i++)
                    wmma::mma_sync(accO[i][j], ah[i], bh_[j], accO[i][j]);
            #pragma unroll
            for (int j = 0; j < 2; j++)
                #pragma unroll
                for (int i = 0; i < 2; i++)
                    wmma::mma_sync(accO[i][j], ah[i], bl_[j], accO[i][j]);
            #pragma unroll
            for (int j = 0; j < 2; j++)
                #pragma unroll
                for (int i = 0; i < 2; i++)
                    wmma::mma_sync(accO[i][j], al[i], bh_[j], accO[i][j]);
        }
        __syncthreads();          // O-MMA done; V buffer free
        if (c + 1 < 32) load_v(c + 1);
    }

    // ---- epilogue: rowinv + normalized split ctx ----
    float tot = rowsum + __shfl_xor_sync(0xFFFFFFFFu, rowsum, 1);
    float inv = 1.0f / tot;
    if (!(tid & 1)) g_rowinv[(size_t)bh * SQ + s0 + row] = inv;

    float* stage = (float*)(sm + 18432);
    #pragma unroll
    for (int i = 0; i < 2; i++)
        #pragma unroll
        for (int j = 0; j < 2; j++)
            wmma::store_matrix_sync(stage + (wy * 32 + i * 16) * 68 + wx * 32 + j * 16,
                                    accO[i][j], 68, wmma::mem_row_major);
    __syncthreads();

    int b = bh >> 3, h = bh & 7;
    size_t obase = ((size_t)(s0 + row) * BB + b) * DD + h * HDIM + half;
    #pragma unroll
    for (int j = 0; j < 8; j++) {
        float4 v = *(float4*)&stage[row * 68 + half + j * 4];
        uint32_t h01, l01, h23, l23;
        split2(v.x * inv, v.y * inv, h01, l01);
        split2(v.z * inv, v.w * inv, h23, l23);
        *(uint2*)(g_cthi + obase + j * 4) = make_uint2(h01, h23);
        *(uint2*)(g_ctlo + obase + j * 4) = make_uint2(l01, l23);
    }
}

// ---------------------------------------------------------------------------
// K4: attn_weights = mean_h exp(scores) * rowinv  (float4 vectorized)
// ---------------------------------------------------------------------------
__global__ void head_avg(float* __restrict__ out_attn) {
    size_t i = (size_t)blockIdx.x * blockDim.x + threadIdx.x;
    size_t n4 = (size_t)BB * SQ * SQ / 4;
    if (i >= n4) return;
    size_t plane4 = (size_t)SQ * SQ / 4;
    size_t b    = i / plane4;
    size_t rem4 = i % plane4;
    size_t s    = rem4 / (SQ / 4);
    float4 sum = make_float4(0.f, 0.f, 0.f, 0.f);
    #pragma unroll
    for (int h = 0; h < HH; h++) {
        size_t bh = b * HH + h;
        float4 v = *((const float4*)(g_scores + bh * SQ * SQ) + rem4);
        float inv = g_rowinv[bh * SQ + s];
        sum.x += __expf(v.x) * inv;
        sum.y += __expf(v.y) * inv;
        sum.z += __expf(v.z) * inv;
        sum.w += __expf(v.w) * inv;
    }
    sum.x *= 0.125f; sum.y *= 0.125f; sum.z *= 0.125f; sum.w *= 0.125f;
    ((float4*)out_attn)[i] = sum;
}

extern "C" void kernel_launch(void* const* d_in, const int* in_sizes, int n_in,
                              void* d_out, int out_size) {
    const float* src   = (const float*)d_in[0];
    const float* in_w  = (const float*)d_in[1];
    const float* in_b  = (const float*)d_in[2];
    const float* out_w = (const float*)d_in[3];
    const float* out_b = (const float*)d_in[4];
    float* out      = (float*)d_out;
    float* attn_out = out + (size_t)SQ * BB * DD;

    __nv_bfloat16 *shi, *slo, *wihi, *wilo, *wohi, *wolo;
    cudaGetSymbolAddress((void**)&shi,  g_shi);
    cudaGetSymbolAddress((void**)&slo,  g_slo);
    cudaGetSymbolAddress((void**)&wihi, g_wihi);
    cudaGetSymbolAddress((void**)&wilo, g_wilo);
    cudaGetSymbolAddress((void**)&wohi, g_wohi);
    cudaGetSymbolAddress((void**)&wolo, g_wolo);

    const int SM_PROJ = 36864 * 2;   // 73728 B
    const int SM_ATTN = 55296 * 2;   // 110592 B
    cudaFuncSetAttribute(qkv_wmma,   cudaFuncAttributeMaxDynamicSharedMemorySize, SM_PROJ);
    cudaFuncSetAttribute(out_wmma,   cudaFuncAttributeMaxDynamicSharedMemorySize, SM_PROJ);
    cudaFuncSetAttribute(attn_fused, cudaFuncAttributeMaxDynamicSharedMemorySize, SM_ATTN);

    int n4s = MROWS * DD / 4, n4i = 3 * DD * DD / 4, n4o = DD * DD / 4;
    split_f32<<<(n4s + 255) / 256, 256>>>(src,  shi,  slo,  n4s);
    split_f32<<<(n4i + 255) / 256, 256>>>(in_w, wihi, wilo, n4i);
    split_f32<<<(n4o + 255) / 256, 256>>>(out_w, wohi, wolo, n4o);

    qkv_wmma<<<dim3(3 * DD / 128, MROWS / 128), 256, SM_PROJ>>>(in_b);
    attn_fused<<<dim3(SQ / 128, BH), 256, SM_ATTN>>>();
    head_avg<<<(unsigned)(((size_t)BB * SQ * SQ / 4 + 255) / 256), 256>>>(attn_out);
    out_wmma<<<dim3(DD / 128, MROWS / 128), 256, SM_PROJ>>>(out_b, out);
}